// round 1
// baseline (speedup 1.0000x reference)
#include <cuda_runtime.h>
#include <math.h>

#define Bb 32
#define Ll 512
#define Hh 768
#define Nn 64
#define NLl 4

// ---------------- device scratch (no allocs allowed) ----------------
__device__ float g_ut[(size_t)Bb * Hh * Ll];   // u transposed [B,H,L]; conv output in-place
__device__ float g_z[(size_t)Bb * Ll * Hh];    // GEMM output [B,L,H]
__device__ float g_K[2 * Hh * Ll];             // conv kernels [2,H,L]
__device__ float g_mu[Bb * Ll];
__device__ float g_rs[Bb * Ll];

__device__ __forceinline__ float gelu_tanh(float x) {
    float x3 = x * x * x;
    return 0.5f * x * (1.0f + tanhf(0.7978845608028654f * (x + 0.044715f * x3)));
}

// ---------------- LN row statistics (mean, rstd) ----------------
__global__ void rowstats_kernel(const float* __restrict__ x) {
    int row = blockIdx.x;
    const float* xr = x + (size_t)row * Hh;
    float s = 0.f, ss = 0.f;
    for (int j = threadIdx.x; j < Hh; j += 256) {
        float v = xr[j];
        s += v; ss += v * v;
    }
    for (int o = 16; o; o >>= 1) {
        s  += __shfl_down_sync(0xffffffffu, s, o);
        ss += __shfl_down_sync(0xffffffffu, ss, o);
    }
    __shared__ float s1[8], s2[8];
    int w = threadIdx.x >> 5;
    if ((threadIdx.x & 31) == 0) { s1[w] = s; s2[w] = ss; }
    __syncthreads();
    if (threadIdx.x == 0) {
        float S = 0.f, SS = 0.f;
        #pragma unroll
        for (int k = 0; k < 8; k++) { S += s1[k]; SS += s2[k]; }
        float mu = S / Hh;
        float var = SS / Hh - mu * mu;
        g_mu[row] = mu;
        g_rs[row] = rsqrtf(var + 1e-5f);
    }
}

// ---------------- LN1 apply + mask + transpose to [B,H,L] ----------------
__global__ void ln1t_kernel(const float* __restrict__ x,
                            const float* __restrict__ w,
                            const float* __restrict__ bsh,
                            const int* __restrict__ mask) {
    __shared__ float tile[32][33];
    int b  = blockIdx.z;
    int l0 = blockIdx.x * 32, h0 = blockIdx.y * 32;
    int tx = threadIdx.x, ty = threadIdx.y;
    float wv = w[h0 + tx], bv = bsh[h0 + tx];
    #pragma unroll
    for (int k = 0; k < 4; k++) {
        int l   = l0 + ty + k * 8;
        int row = b * Ll + l;
        float v  = x[(size_t)row * Hh + h0 + tx];
        float mf = (float)mask[row];
        tile[ty + k * 8][tx] = ((v - g_mu[row]) * g_rs[row] * wv + bv) * mf;
    }
    __syncthreads();
    #pragma unroll
    for (int k = 0; k < 4; k++) {
        int h = h0 + ty + k * 8;
        g_ut[((size_t)b * Hh + h) * Ll + l0 + tx] = tile[tx][ty + k * 8];
    }
}

// ---------------- S4D kernel K[2,H,L] precompute ----------------
__global__ void kcomp_kernel(int layer,
                             const float* __restrict__ log_dt,
                             const float* __restrict__ A_re,
                             const float* __restrict__ A_im,
                             const float* __restrict__ C_re,
                             const float* __restrict__ C_im) {
    int h = blockIdx.x;
    __shared__ float s_ar[Nn], s_ai[Nn], s_c0r[Nn], s_c0i[Nn], s_c1r[Nn], s_c1i[Nn];
    int t = threadIdx.x;
    if (t < Nn) {
        float dt = expf(log_dt[layer * Hh + h]);
        float Ar = -expf(A_re[((size_t)layer * Hh + h) * Nn + t]);
        float Ai = A_im[((size_t)layer * Hh + h) * Nn + t];
        float ar = dt * Ar, ai = dt * Ai;
        float er = expf(ar), sn, cs;
        sincosf(ai, &sn, &cs);
        float zr = er * cs - 1.0f, zi = er * sn;
        float den = Ar * Ar + Ai * Ai;
        float wr = (zr * Ar + zi * Ai) / den;
        float wi = (zi * Ar - zr * Ai) / den;
        size_t c0 = ((size_t)(layer * 2 + 0) * Hh + h) * Nn + t;
        size_t c1 = ((size_t)(layer * 2 + 1) * Hh + h) * Nn + t;
        float cr0 = C_re[c0], ci0 = C_im[c0];
        float cr1 = C_re[c1], ci1 = C_im[c1];
        s_ar[t] = ar; s_ai[t] = ai;
        s_c0r[t] = cr0 * wr - ci0 * wi;  s_c0i[t] = cr0 * wi + ci0 * wr;
        s_c1r[t] = cr1 * wr - ci1 * wi;  s_c1i[t] = cr1 * wi + ci1 * wr;
    }
    __syncthreads();
    for (int l = t; l < Ll; l += 256) {
        float k0 = 0.f, k1 = 0.f;
        float fl = (float)l;
        #pragma unroll 4
        for (int n = 0; n < Nn; n++) {
            float e = expf(s_ar[n] * fl);
            float sn, cs;
            sincosf(s_ai[n] * fl, &sn, &cs);
            float vr = e * cs, vi = e * sn;
            k0 += s_c0r[n] * vr - s_c0i[n] * vi;
            k1 += s_c1r[n] * vr - s_c1i[n] * vi;
        }
        g_K[(size_t)h * Ll + l]              = 2.0f * k0;
        g_K[((size_t)Hh + h) * Ll + l]       = 2.0f * k1;
    }
}

// ---------------- bidirectional conv + D*u + GELU (in-place on g_ut) ----------------
__global__ void __launch_bounds__(128) conv_kernel(const float* __restrict__ Dvec) {
    int bx = blockIdx.x;
    int b = bx / Hh, h = bx - b * Hh;
    __shared__ float up[2048];   // zero-padded u: valid data at [512,1024)
    __shared__ float sk0[512], sk1[512];
    int t = threadIdx.x;
    float* urow = g_ut + ((size_t)b * Hh + h) * Ll;
    const float* k0row = g_K + (size_t)h * Ll;
    const float* k1row = g_K + ((size_t)Hh + h) * Ll;
    for (int i = t; i < 512; i += 128) {
        up[i] = 0.f;
        up[1024 + i] = 0.f;
        up[1536 + i] = 0.f;
        up[512 + i] = urow[i];
        sk0[i] = k0row[i];
        sk1[i] = k1row[i];
    }
    __syncthreads();

    int lb = t * 4;
    float acc0 = 0.f, acc1 = 0.f, acc2 = 0.f, acc3 = 0.f;

    // causal: y[l] += sum_t k0[t] * up[512 + l - t]
    for (int t0 = 0; t0 < 512; t0 += 8) {
        float kk[8];
        #pragma unroll
        for (int q = 0; q < 8; q++) kk[q] = sk0[t0 + q];
        float w[11];
        int base = 512 + lb - t0 - 7;
        #pragma unroll
        for (int q = 0; q < 11; q++) w[q] = up[base + q];
        #pragma unroll
        for (int tu = 0; tu < 8; tu++) {
            acc0 += kk[tu] * w[7  - tu];
            acc1 += kk[tu] * w[8  - tu];
            acc2 += kk[tu] * w[9  - tu];
            acc3 += kk[tu] * w[10 - tu];
        }
    }
    // anticausal: y[l] += sum_s k1[s] * up[512 + l + 1 + s]
    for (int s0 = 0; s0 < 512; s0 += 8) {
        float kk[8];
        #pragma unroll
        for (int q = 0; q < 8; q++) kk[q] = sk1[s0 + q];
        float w[11];
        int base = 512 + lb + 1 + s0;
        #pragma unroll
        for (int q = 0; q < 11; q++) w[q] = up[base + q];
        #pragma unroll
        for (int su = 0; su < 8; su++) {
            acc0 += kk[su] * w[su + 0];
            acc1 += kk[su] * w[su + 1];
            acc2 += kk[su] * w[su + 2];
            acc3 += kk[su] * w[su + 3];
        }
    }

    float dv = Dvec[h];
    float uv0 = up[512 + lb + 0];
    float uv1 = up[512 + lb + 1];
    float uv2 = up[512 + lb + 2];
    float uv3 = up[512 + lb + 3];
    urow[lb + 0] = gelu_tanh(acc0 + dv * uv0);
    urow[lb + 1] = gelu_tanh(acc1 + dv * uv1);
    urow[lb + 2] = gelu_tanh(acc2 + dv * uv2);
    urow[lb + 3] = gelu_tanh(acc3 + dv * uv3);
}

// ---------------- z[b,l,o] = sum_h y_t[b,h,l] * Wout[o,h] + bout[o] ----------------
__global__ void __launch_bounds__(256) gemm_kernel(const float* __restrict__ Wout,
                                                   const float* __restrict__ bout) {
    __shared__ float sY[8][128];
    __shared__ float sW[8][132];   // padded, row stride 528B (16B-multiple)

    int tid = threadIdx.x;
    int m0 = blockIdx.y * 128, o0 = blockIdx.x * 128;
    int b  = m0 / Ll;
    int l0 = m0 - b * Ll;
    const float* ybase = g_ut + (size_t)b * Hh * Ll;

    int yk = tid >> 5, ym = (tid & 31) * 4;    // y tile loader coords
    int wn = tid >> 1, wk4 = (tid & 1) * 4;    // W tile loader coords
    int ty = tid >> 4, tx = tid & 15;

    float acc[8][8];
    #pragma unroll
    for (int i = 0; i < 8; i++)
        #pragma unroll
        for (int j = 0; j < 8; j++) acc[i][j] = 0.f;

    for (int k0 = 0; k0 < Hh; k0 += 8) {
        float4 yv = *(const float4*)&ybase[(size_t)(k0 + yk) * Ll + l0 + ym];
        float4 wv = *(const float4*)&Wout[(size_t)(o0 + wn) * Hh + k0 + wk4];
        __syncthreads();
        *(float4*)&sY[yk][ym] = yv;
        sW[wk4 + 0][wn] = wv.x;
        sW[wk4 + 1][wn] = wv.y;
        sW[wk4 + 2][wn] = wv.z;
        sW[wk4 + 3][wn] = wv.w;
        __syncthreads();
        #pragma unroll
        for (int kk = 0; kk < 8; kk++) {
            float4 a0 = *(const float4*)&sY[kk][ty * 8];
            float4 a1 = *(const float4*)&sY[kk][ty * 8 + 4];
            float4 b0 = *(const float4*)&sW[kk][tx * 8];
            float4 b1 = *(const float4*)&sW[kk][tx * 8 + 4];
            float av[8] = {a0.x, a0.y, a0.z, a0.w, a1.x, a1.y, a1.z, a1.w};
            float bv[8] = {b0.x, b0.y, b0.z, b0.w, b1.x, b1.y, b1.z, b1.w};
            #pragma unroll
            for (int i = 0; i < 8; i++)
                #pragma unroll
                for (int j = 0; j < 8; j++)
                    acc[i][j] += av[i] * bv[j];
        }
    }

    float bo[8];
    #pragma unroll
    for (int j = 0; j < 8; j++) bo[j] = bout[o0 + tx * 8 + j];
    #pragma unroll
    for (int i = 0; i < 8; i++) {
        int m = m0 + ty * 8 + i;
        float* zr = g_z + (size_t)m * Hh + o0 + tx * 8;
        float4 o0v = make_float4(acc[i][0] + bo[0], acc[i][1] + bo[1],
                                 acc[i][2] + bo[2], acc[i][3] + bo[3]);
        float4 o1v = make_float4(acc[i][4] + bo[4], acc[i][5] + bo[5],
                                 acc[i][6] + bo[6], acc[i][7] + bo[7]);
        *(float4*)&zr[0] = o0v;
        *(float4*)&zr[4] = o1v;
    }
}

// ---------------- LN2 + residual: x += LN(z) ----------------
__global__ void ln2res_kernel(const float* __restrict__ w,
                              const float* __restrict__ bsh,
                              float* __restrict__ x) {
    int row = blockIdx.x;
    const float* zr = g_z + (size_t)row * Hh;
    float v[3];
    float s = 0.f, ss = 0.f;
    #pragma unroll
    for (int q = 0; q < 3; q++) {
        v[q] = zr[threadIdx.x + q * 256];
        s += v[q]; ss += v[q] * v[q];
    }
    for (int o = 16; o; o >>= 1) {
        s  += __shfl_down_sync(0xffffffffu, s, o);
        ss += __shfl_down_sync(0xffffffffu, ss, o);
    }
    __shared__ float s1[8], s2[8];
    __shared__ float smu, srs;
    int wi = threadIdx.x >> 5;
    if ((threadIdx.x & 31) == 0) { s1[wi] = s; s2[wi] = ss; }
    __syncthreads();
    if (threadIdx.x == 0) {
        float S = 0.f, SS = 0.f;
        #pragma unroll
        for (int k = 0; k < 8; k++) { S += s1[k]; SS += s2[k]; }
        float mu = S / Hh;
        float var = SS / Hh - mu * mu;
        smu = mu;
        srs = rsqrtf(var + 1e-5f);
    }
    __syncthreads();
    float mu = smu, rs = srs;
    #pragma unroll
    for (int q = 0; q < 3; q++) {
        int j = threadIdx.x + q * 256;
        size_t idx = (size_t)row * Hh + j;
        x[idx] = x[idx] + ((v[q] - mu) * rs * w[j] + bsh[j]);
    }
}

// ---------------- launch ----------------
extern "C" void kernel_launch(void* const* d_in, const int* in_sizes, int n_in,
                              void* d_out, int out_size) {
    const float* x_in   = (const float*)d_in[0];
    const int*   mask   = (const int*)  d_in[1];
    const float* ln1_w  = (const float*)d_in[2];
    const float* ln1_b  = (const float*)d_in[3];
    const float* log_dt = (const float*)d_in[4];
    const float* A_re   = (const float*)d_in[5];
    const float* A_im   = (const float*)d_in[6];
    const float* C_re   = (const float*)d_in[7];
    const float* C_im   = (const float*)d_in[8];
    const float* Dv     = (const float*)d_in[9];
    const float* Wout   = (const float*)d_in[10];
    const float* bout   = (const float*)d_in[11];
    const float* ln2_w  = (const float*)d_in[12];
    const float* ln2_b  = (const float*)d_in[13];
    float* x = (float*)d_out;

    cudaMemcpyAsync(x, x_in, sizeof(float) * (size_t)Bb * Ll * Hh,
                    cudaMemcpyDeviceToDevice, 0);

    for (int i = 0; i < NLl; i++) {
        kcomp_kernel<<<Hh, 256>>>(i, log_dt, A_re, A_im, C_re, C_im);
        rowstats_kernel<<<Bb * Ll, 256>>>(x);
        ln1t_kernel<<<dim3(Ll / 32, Hh / 32, Bb), dim3(32, 8)>>>(
            x, ln1_w + i * Hh, ln1_b + i * Hh, mask);
        conv_kernel<<<Bb * Hh, 128>>>(Dv + i * Hh);
        gemm_kernel<<<dim3(Hh / 128, Bb * Ll / 128), 256>>>(
            Wout + (size_t)i * Hh * Hh, bout + i * Hh);
        ln2res_kernel<<<Bb * Ll, 256>>>(ln2_w + i * Hh, ln2_b + i * Hh, x);
    }
}

// round 2
// speedup vs baseline: 2.1493x; 2.1493x over previous
#include <cuda_runtime.h>
#include <math.h>

#define Bb 32
#define Ll 512
#define Hh 768
#define Nn 64
#define NLl 4

// ---------------- device scratch (no allocs allowed) ----------------
__device__ __align__(16) float g_ut[(size_t)Bb * Hh * Ll];   // u transposed [B,H,L]; conv output in-place
__device__ __align__(16) float g_z[(size_t)Bb * Ll * Hh];    // GEMM output [B,L,H]
__device__ __align__(16) float g_K[2 * Hh * Ll];             // conv kernels [2,H,L]
__device__ float g_mu[Bb * Ll];
__device__ float g_rs[Bb * Ll];

__device__ __forceinline__ float gelu_tanh(float x) {
    float x3 = x * x * x;
    return 0.5f * x * (1.0f + tanhf(0.7978845608028654f * (x + 0.044715f * x3)));
}

// ---------------- LN row statistics (mean, rstd) ----------------
__global__ void rowstats_kernel(const float* __restrict__ x) {
    int row = blockIdx.x;
    const float* xr = x + (size_t)row * Hh;
    float s = 0.f, ss = 0.f;
    for (int j = threadIdx.x; j < Hh; j += 256) {
        float v = xr[j];
        s += v; ss += v * v;
    }
    for (int o = 16; o; o >>= 1) {
        s  += __shfl_down_sync(0xffffffffu, s, o);
        ss += __shfl_down_sync(0xffffffffu, ss, o);
    }
    __shared__ float s1[8], s2[8];
    int w = threadIdx.x >> 5;
    if ((threadIdx.x & 31) == 0) { s1[w] = s; s2[w] = ss; }
    __syncthreads();
    if (threadIdx.x == 0) {
        float S = 0.f, SS = 0.f;
        #pragma unroll
        for (int k = 0; k < 8; k++) { S += s1[k]; SS += s2[k]; }
        float mu = S / Hh;
        float var = SS / Hh - mu * mu;
        g_mu[row] = mu;
        g_rs[row] = rsqrtf(var + 1e-5f);
    }
}

// ---------------- LN1 apply + mask + transpose to [B,H,L] ----------------
__global__ void ln1t_kernel(const float* __restrict__ x,
                            const float* __restrict__ w,
                            const float* __restrict__ bsh,
                            const int* __restrict__ mask) {
    __shared__ float tile[32][33];
    int b  = blockIdx.z;
    int l0 = blockIdx.x * 32, h0 = blockIdx.y * 32;
    int tx = threadIdx.x, ty = threadIdx.y;
    float wv = w[h0 + tx], bv = bsh[h0 + tx];
    #pragma unroll
    for (int k = 0; k < 4; k++) {
        int l   = l0 + ty + k * 8;
        int row = b * Ll + l;
        float v  = x[(size_t)row * Hh + h0 + tx];
        float mf = (float)mask[row];
        tile[ty + k * 8][tx] = ((v - g_mu[row]) * g_rs[row] * wv + bv) * mf;
    }
    __syncthreads();
    #pragma unroll
    for (int k = 0; k < 4; k++) {
        int h = h0 + ty + k * 8;
        g_ut[((size_t)b * Hh + h) * Ll + l0 + tx] = tile[tx][ty + k * 8];
    }
}

// ---------------- S4D kernel K[2,H,L] precompute ----------------
// 64 threads per h. Thread t owns l in [8t, 8t+8). Per n: one expf+sincosf at the
// chunk start, then 7 complex-recurrence steps with step constant e^{dtA}.
__global__ void __launch_bounds__(64) kcomp_kernel(int layer,
                             const float* __restrict__ log_dt,
                             const float* __restrict__ A_re,
                             const float* __restrict__ A_im,
                             const float* __restrict__ C_re,
                             const float* __restrict__ C_im) {
    int h = blockIdx.x;
    __shared__ float s_ar[Nn], s_ai[Nn];
    __shared__ float s_sr[Nn], s_si[Nn];   // step = e^{dtA}
    __shared__ float s_c0r[Nn], s_c0i[Nn], s_c1r[Nn], s_c1i[Nn];
    int t = threadIdx.x;
    {
        float dt = expf(log_dt[layer * Hh + h]);
        float Ar = -expf(A_re[((size_t)layer * Hh + h) * Nn + t]);
        float Ai = A_im[((size_t)layer * Hh + h) * Nn + t];
        float ar = dt * Ar, ai = dt * Ai;
        float er = expf(ar), sn, cs;
        sincosf(ai, &sn, &cs);
        float zr = er * cs - 1.0f, zi = er * sn;
        float den = Ar * Ar + Ai * Ai;
        float wr = (zr * Ar + zi * Ai) / den;
        float wi = (zi * Ar - zr * Ai) / den;
        size_t c0 = ((size_t)(layer * 2 + 0) * Hh + h) * Nn + t;
        size_t c1 = ((size_t)(layer * 2 + 1) * Hh + h) * Nn + t;
        float cr0 = C_re[c0], ci0 = C_im[c0];
        float cr1 = C_re[c1], ci1 = C_im[c1];
        s_ar[t] = ar; s_ai[t] = ai;
        s_sr[t] = er * cs; s_si[t] = er * sn;
        s_c0r[t] = cr0 * wr - ci0 * wi;  s_c0i[t] = cr0 * wi + ci0 * wr;
        s_c1r[t] = cr1 * wr - ci1 * wi;  s_c1i[t] = cr1 * wi + ci1 * wr;
    }
    __syncthreads();

    int l0 = t * 8;
    float fl0 = (float)l0;
    float k0a[8], k1a[8];
    #pragma unroll
    for (int j = 0; j < 8; j++) { k0a[j] = 0.f; k1a[j] = 0.f; }

    for (int n = 0; n < Nn; n++) {
        float ar = s_ar[n], ai = s_ai[n];
        float e0 = expf(ar * fl0);
        float sn, cs;
        sincosf(ai * fl0, &sn, &cs);
        float vr = e0 * cs, vi = e0 * sn;
        float sr = s_sr[n], si = s_si[n];
        float c0r = s_c0r[n], c0i = s_c0i[n];
        float c1r = s_c1r[n], c1i = s_c1i[n];
        #pragma unroll
        for (int j = 0; j < 8; j++) {
            k0a[j] += c0r * vr - c0i * vi;
            k1a[j] += c1r * vr - c1i * vi;
            float nvr = vr * sr - vi * si;
            float nvi = vr * si + vi * sr;
            vr = nvr; vi = nvi;
        }
    }
    #pragma unroll
    for (int j = 0; j < 8; j++) {
        g_K[(size_t)h * Ll + l0 + j]        = 2.0f * k0a[j];
        g_K[((size_t)Hh + h) * Ll + l0 + j] = 2.0f * k1a[j];
    }
}

// ---------------- bidirectional conv + D*u + GELU (in-place on g_ut) ----------------
// All smem window loads are 16B-aligned LDS.128 (conflict-free); taps via broadcast LDS.128.
__global__ void __launch_bounds__(128) conv_kernel(const float* __restrict__ Dvec) {
    int bx = blockIdx.x;
    int b = bx / Hh, h = bx - b * Hh;
    __shared__ __align__(16) float up[2048];   // zero-padded u: valid data at [512,1024)
    __shared__ __align__(16) float sk0[512], sk1[512];
    int t = threadIdx.x;
    float* urow = g_ut + ((size_t)b * Hh + h) * Ll;
    const float* k0row = g_K + (size_t)h * Ll;
    const float* k1row = g_K + ((size_t)Hh + h) * Ll;

    // vectorized fill: 512 floats = 128 float4, one per thread
    float4 z4 = make_float4(0.f, 0.f, 0.f, 0.f);
    ((float4*)up)[t]       = z4;                           // [0,512)
    ((float4*)up)[256 + t] = z4;                           // [1024,1536)
    ((float4*)up)[384 + t] = z4;                           // [1536,2048)
    ((float4*)up)[128 + t] = ((const float4*)urow)[t];     // [512,1024)
    ((float4*)sk0)[t] = ((const float4*)k0row)[t];
    ((float4*)sk1)[t] = ((const float4*)k1row)[t];
    __syncthreads();

    int lb = t * 4;
    float acc0 = 0.f, acc1 = 0.f, acc2 = 0.f, acc3 = 0.f;

    // causal: y[l] += sum_t k0[t] * u[l-t]
    for (int t0 = 0; t0 < 512; t0 += 8) {
        float4 ka = *(const float4*)&sk0[t0];
        float4 kb = *(const float4*)&sk0[t0 + 4];
        float kk[8] = {ka.x, ka.y, ka.z, ka.w, kb.x, kb.y, kb.z, kb.w};
        int base = 512 + lb - t0 - 8;     // 16B-aligned
        float w[12];
        *(float4*)&w[0] = *(const float4*)&up[base];
        *(float4*)&w[4] = *(const float4*)&up[base + 4];
        *(float4*)&w[8] = *(const float4*)&up[base + 8];
        #pragma unroll
        for (int tu = 0; tu < 8; tu++) {
            acc0 += kk[tu] * w[8  - tu];
            acc1 += kk[tu] * w[9  - tu];
            acc2 += kk[tu] * w[10 - tu];
            acc3 += kk[tu] * w[11 - tu];
        }
    }
    // anticausal: y[l] += sum_s k1[s] * u[l+1+s]
    for (int s0 = 0; s0 < 512; s0 += 8) {
        float4 ka = *(const float4*)&sk1[s0];
        float4 kb = *(const float4*)&sk1[s0 + 4];
        float kk[8] = {ka.x, ka.y, ka.z, ka.w, kb.x, kb.y, kb.z, kb.w};
        int base = 512 + lb + s0;         // 16B-aligned
        float w[12];
        *(float4*)&w[0] = *(const float4*)&up[base];
        *(float4*)&w[4] = *(const float4*)&up[base + 4];
        *(float4*)&w[8] = *(const float4*)&up[base + 8];
        #pragma unroll
        for (int su = 0; su < 8; su++) {
            acc0 += kk[su] * w[su + 1];
            acc1 += kk[su] * w[su + 2];
            acc2 += kk[su] * w[su + 3];
            acc3 += kk[su] * w[su + 4];
        }
    }

    float dv = Dvec[h];
    float uv0 = up[512 + lb + 0];
    float uv1 = up[512 + lb + 1];
    float uv2 = up[512 + lb + 2];
    float uv3 = up[512 + lb + 3];
    urow[lb + 0] = gelu_tanh(acc0 + dv * uv0);
    urow[lb + 1] = gelu_tanh(acc1 + dv * uv1);
    urow[lb + 2] = gelu_tanh(acc2 + dv * uv2);
    urow[lb + 3] = gelu_tanh(acc3 + dv * uv3);
}

// ---------------- z[b,l,o] = sum_h y_t[b,h,l] * Wout[o,h] + bout[o] ----------------
__global__ void __launch_bounds__(256) gemm_kernel(const float* __restrict__ Wout,
                                                   const float* __restrict__ bout) {
    __shared__ float sY[8][128];
    __shared__ float sW[8][132];   // padded, row stride 528B (16B-multiple)

    int tid = threadIdx.x;
    int m0 = blockIdx.y * 128, o0 = blockIdx.x * 128;
    int b  = m0 / Ll;
    int l0 = m0 - b * Ll;
    const float* ybase = g_ut + (size_t)b * Hh * Ll;

    int yk = tid >> 5, ym = (tid & 31) * 4;    // y tile loader coords
    int wn = tid >> 1, wk4 = (tid & 1) * 4;    // W tile loader coords
    int ty = tid >> 4, tx = tid & 15;

    float acc[8][8];
    #pragma unroll
    for (int i = 0; i < 8; i++)
        #pragma unroll
        for (int j = 0; j < 8; j++) acc[i][j] = 0.f;

    for (int k0 = 0; k0 < Hh; k0 += 8) {
        float4 yv = *(const float4*)&ybase[(size_t)(k0 + yk) * Ll + l0 + ym];
        float4 wv = *(const float4*)&Wout[(size_t)(o0 + wn) * Hh + k0 + wk4];
        __syncthreads();
        *(float4*)&sY[yk][ym] = yv;
        sW[wk4 + 0][wn] = wv.x;
        sW[wk4 + 1][wn] = wv.y;
        sW[wk4 + 2][wn] = wv.z;
        sW[wk4 + 3][wn] = wv.w;
        __syncthreads();
        #pragma unroll
        for (int kk = 0; kk < 8; kk++) {
            float4 a0 = *(const float4*)&sY[kk][ty * 8];
            float4 a1 = *(const float4*)&sY[kk][ty * 8 + 4];
            float4 b0 = *(const float4*)&sW[kk][tx * 8];
            float4 b1 = *(const float4*)&sW[kk][tx * 8 + 4];
            float av[8] = {a0.x, a0.y, a0.z, a0.w, a1.x, a1.y, a1.z, a1.w};
            float bv[8] = {b0.x, b0.y, b0.z, b0.w, b1.x, b1.y, b1.z, b1.w};
            #pragma unroll
            for (int i = 0; i < 8; i++)
                #pragma unroll
                for (int j = 0; j < 8; j++)
                    acc[i][j] += av[i] * bv[j];
        }
    }

    float bo[8];
    #pragma unroll
    for (int j = 0; j < 8; j++) bo[j] = bout[o0 + tx * 8 + j];
    #pragma unroll
    for (int i = 0; i < 8; i++) {
        int m = m0 + ty * 8 + i;
        float* zr = g_z + (size_t)m * Hh + o0 + tx * 8;
        float4 o0v = make_float4(acc[i][0] + bo[0], acc[i][1] + bo[1],
                                 acc[i][2] + bo[2], acc[i][3] + bo[3]);
        float4 o1v = make_float4(acc[i][4] + bo[4], acc[i][5] + bo[5],
                                 acc[i][6] + bo[6], acc[i][7] + bo[7]);
        *(float4*)&zr[0] = o0v;
        *(float4*)&zr[4] = o1v;
    }
}

// ---------------- LN2 + residual: x += LN(z) ----------------
__global__ void ln2res_kernel(const float* __restrict__ w,
                              const float* __restrict__ bsh,
                              float* __restrict__ x) {
    int row = blockIdx.x;
    const float* zr = g_z + (size_t)row * Hh;
    float v[3];
    float s = 0.f, ss = 0.f;
    #pragma unroll
    for (int q = 0; q < 3; q++) {
        v[q] = zr[threadIdx.x + q * 256];
        s += v[q]; ss += v[q] * v[q];
    }
    for (int o = 16; o; o >>= 1) {
        s  += __shfl_down_sync(0xffffffffu, s, o);
        ss += __shfl_down_sync(0xffffffffu, ss, o);
    }
    __shared__ float s1[8], s2[8];
    __shared__ float smu, srs;
    int wi = threadIdx.x >> 5;
    if ((threadIdx.x & 31) == 0) { s1[wi] = s; s2[wi] = ss; }
    __syncthreads();
    if (threadIdx.x == 0) {
        float S = 0.f, SS = 0.f;
        #pragma unroll
        for (int k = 0; k < 8; k++) { S += s1[k]; SS += s2[k]; }
        float mu = S / Hh;
        float var = SS / Hh - mu * mu;
        smu = mu;
        srs = rsqrtf(var + 1e-5f);
    }
    __syncthreads();
    float mu = smu, rs = srs;
    #pragma unroll
    for (int q = 0; q < 3; q++) {
        int j = threadIdx.x + q * 256;
        size_t idx = (size_t)row * Hh + j;
        x[idx] = x[idx] + ((v[q] - mu) * rs * w[j] + bsh[j]);
    }
}

// ---------------- launch ----------------
extern "C" void kernel_launch(void* const* d_in, const int* in_sizes, int n_in,
                              void* d_out, int out_size) {
    const float* x_in   = (const float*)d_in[0];
    const int*   mask   = (const int*)  d_in[1];
    const float* ln1_w  = (const float*)d_in[2];
    const float* ln1_b  = (const float*)d_in[3];
    const float* log_dt = (const float*)d_in[4];
    const float* A_re   = (const float*)d_in[5];
    const float* A_im   = (const float*)d_in[6];
    const float* C_re   = (const float*)d_in[7];
    const float* C_im   = (const float*)d_in[8];
    const float* Dv     = (const float*)d_in[9];
    const float* Wout   = (const float*)d_in[10];
    const float* bout   = (const float*)d_in[11];
    const float* ln2_w  = (const float*)d_in[12];
    const float* ln2_b  = (const float*)d_in[13];
    float* x = (float*)d_out;

    cudaMemcpyAsync(x, x_in, sizeof(float) * (size_t)Bb * Ll * Hh,
                    cudaMemcpyDeviceToDevice, 0);

    for (int i = 0; i < NLl; i++) {
        kcomp_kernel<<<Hh, 64>>>(i, log_dt, A_re, A_im, C_re, C_im);
        rowstats_kernel<<<Bb * Ll, 256>>>(x);
        ln1t_kernel<<<dim3(Ll / 32, Hh / 32, Bb), dim3(32, 8)>>>(
            x, ln1_w + i * Hh, ln1_b + i * Hh, mask);
        conv_kernel<<<Bb * Hh, 128>>>(Dv + i * Hh);
        gemm_kernel<<<dim3(Hh / 128, Bb * Ll / 128), 256>>>(
            Wout + (size_t)i * Hh * Hh, bout + i * Hh);
        ln2res_kernel<<<Bb * Ll, 256>>>(ln2_w + i * Hh, ln2_b + i * Hh, x);
    }
}

// round 4
// speedup vs baseline: 3.6907x; 1.7172x over previous
#include <cuda_runtime.h>
#include <cuda_bf16.h>
#include <math.h>
#include <stdint.h>

#define Bb 32
#define Ll 512
#define Hh 768
#define Nn 64
#define NLl 4

// ---------------- device scratch (no allocs allowed) ----------------
__device__ __align__(16) float g_ut[(size_t)Bb * Hh * Ll];   // u transposed [B,H,L]; conv output in-place
__device__ __align__(16) float g_z[(size_t)Bb * Ll * Hh];    // GEMM output [B,L,H]
__device__ __align__(16) float g_K[2 * Hh * Ll];             // conv kernels [2,H,L]
__device__ float g_mu[Bb * Ll];
__device__ float g_rs[Bb * Ll];
// bf16 hi/lo operands for tensor-core GEMM
__device__ __align__(16) __nv_bfloat16 g_yhi[(size_t)Bb * Ll * Hh];
__device__ __align__(16) __nv_bfloat16 g_ylo[(size_t)Bb * Ll * Hh];
__device__ __align__(16) __nv_bfloat16 g_whi[NLl * Hh * Hh];
__device__ __align__(16) __nv_bfloat16 g_wlo[NLl * Hh * Hh];

__device__ __forceinline__ float gelu_tanh(float x) {
    float x3 = x * x * x;
    return 0.5f * x * (1.0f + tanhf(0.7978845608028654f * (x + 0.044715f * x3)));
}

__device__ __forceinline__ uint32_t smem_u32(const void* p) {
    uint32_t a;
    asm("{ .reg .u64 t; cvta.to.shared.u64 t, %1; cvt.u32.u64 %0, t; }" : "=r"(a) : "l"(p));
    return a;
}
__device__ __forceinline__ void cp16(uint32_t saddr, const void* g) {
    asm volatile("cp.async.ca.shared.global [%0], [%1], 16;" :: "r"(saddr), "l"(g) : "memory");
}
__device__ __forceinline__ void cp_commit() { asm volatile("cp.async.commit_group;" ::: "memory"); }
__device__ __forceinline__ void cp_wait1()  { asm volatile("cp.async.wait_group 1;" ::: "memory"); }
__device__ __forceinline__ void cp_wait0()  { asm volatile("cp.async.wait_group 0;" ::: "memory"); }
__device__ __forceinline__ void ldmx4(uint32_t* r, uint32_t addr) {
    asm volatile("ldmatrix.sync.aligned.m8n8.x4.shared.b16 {%0,%1,%2,%3}, [%4];"
        : "=r"(r[0]), "=r"(r[1]), "=r"(r[2]), "=r"(r[3]) : "r"(addr));
}
__device__ __forceinline__ void mma_bf16(float* c, const uint32_t* a, uint32_t b0, uint32_t b1) {
    asm volatile("mma.sync.aligned.m16n8k16.row.col.f32.bf16.bf16.f32 "
        "{%0,%1,%2,%3}, {%4,%5,%6,%7}, {%8,%9}, {%0,%1,%2,%3};"
        : "+f"(c[0]), "+f"(c[1]), "+f"(c[2]), "+f"(c[3])
        : "r"(a[0]), "r"(a[1]), "r"(a[2]), "r"(a[3]), "r"(b0), "r"(b1));
}

// ---------------- LN row statistics (mean, rstd) ----------------
__global__ void rowstats_kernel(const float* __restrict__ x) {
    int row = blockIdx.x;
    const float* xr = x + (size_t)row * Hh;
    float s = 0.f, ss = 0.f;
    for (int j = threadIdx.x; j < Hh; j += 256) {
        float v = xr[j];
        s += v; ss += v * v;
    }
    for (int o = 16; o; o >>= 1) {
        s  += __shfl_down_sync(0xffffffffu, s, o);
        ss += __shfl_down_sync(0xffffffffu, ss, o);
    }
    __shared__ float s1[8], s2[8];
    int w = threadIdx.x >> 5;
    if ((threadIdx.x & 31) == 0) { s1[w] = s; s2[w] = ss; }
    __syncthreads();
    if (threadIdx.x == 0) {
        float S = 0.f, SS = 0.f;
        #pragma unroll
        for (int k = 0; k < 8; k++) { S += s1[k]; SS += s2[k]; }
        float mu = S / Hh;
        float var = SS / Hh - mu * mu;
        g_mu[row] = mu;
        g_rs[row] = rsqrtf(var + 1e-5f);
    }
}

// ---------------- LN1 apply + mask + transpose to [B,H,L] ----------------
__global__ void ln1t_kernel(const float* __restrict__ x,
                            const float* __restrict__ w,
                            const float* __restrict__ bsh,
                            const int* __restrict__ mask) {
    __shared__ float tile[32][33];
    int b  = blockIdx.z;
    int l0 = blockIdx.x * 32, h0 = blockIdx.y * 32;
    int tx = threadIdx.x, ty = threadIdx.y;
    float wv = w[h0 + tx], bv = bsh[h0 + tx];
    #pragma unroll
    for (int k = 0; k < 4; k++) {
        int l   = l0 + ty + k * 8;
        int row = b * Ll + l;
        float v  = x[(size_t)row * Hh + h0 + tx];
        float mf = (float)mask[row];
        tile[ty + k * 8][tx] = ((v - g_mu[row]) * g_rs[row] * wv + bv) * mf;
    }
    __syncthreads();
    #pragma unroll
    for (int k = 0; k < 4; k++) {
        int h = h0 + ty + k * 8;
        g_ut[((size_t)b * Hh + h) * Ll + l0 + tx] = tile[tx][ty + k * 8];
    }
}

// ---------------- S4D kernel K[2,H,L] precompute ----------------
__global__ void __launch_bounds__(64) kcomp_kernel(int layer,
                             const float* __restrict__ log_dt,
                             const float* __restrict__ A_re,
                             const float* __restrict__ A_im,
                             const float* __restrict__ C_re,
                             const float* __restrict__ C_im) {
    int h = blockIdx.x;
    __shared__ float s_ar[Nn], s_ai[Nn];
    __shared__ float s_sr[Nn], s_si[Nn];   // step = e^{dtA}
    __shared__ float s_c0r[Nn], s_c0i[Nn], s_c1r[Nn], s_c1i[Nn];
    int t = threadIdx.x;
    {
        float dt = expf(log_dt[layer * Hh + h]);
        float Ar = -expf(A_re[((size_t)layer * Hh + h) * Nn + t]);
        float Ai = A_im[((size_t)layer * Hh + h) * Nn + t];
        float ar = dt * Ar, ai = dt * Ai;
        float er = expf(ar), sn, cs;
        sincosf(ai, &sn, &cs);
        float zr = er * cs - 1.0f, zi = er * sn;
        float den = Ar * Ar + Ai * Ai;
        float wr = (zr * Ar + zi * Ai) / den;
        float wi = (zi * Ar - zr * Ai) / den;
        size_t c0 = ((size_t)(layer * 2 + 0) * Hh + h) * Nn + t;
        size_t c1 = ((size_t)(layer * 2 + 1) * Hh + h) * Nn + t;
        float cr0 = C_re[c0], ci0 = C_im[c0];
        float cr1 = C_re[c1], ci1 = C_im[c1];
        s_ar[t] = ar; s_ai[t] = ai;
        s_sr[t] = er * cs; s_si[t] = er * sn;
        s_c0r[t] = cr0 * wr - ci0 * wi;  s_c0i[t] = cr0 * wi + ci0 * wr;
        s_c1r[t] = cr1 * wr - ci1 * wi;  s_c1i[t] = cr1 * wi + ci1 * wr;
    }
    __syncthreads();

    int l0 = t * 8;
    float fl0 = (float)l0;
    float k0a[8], k1a[8];
    #pragma unroll
    for (int j = 0; j < 8; j++) { k0a[j] = 0.f; k1a[j] = 0.f; }

    for (int n = 0; n < Nn; n++) {
        float ar = s_ar[n], ai = s_ai[n];
        float e0 = expf(ar * fl0);
        float sn, cs;
        sincosf(ai * fl0, &sn, &cs);
        float vr = e0 * cs, vi = e0 * sn;
        float sr = s_sr[n], si = s_si[n];
        float c0r = s_c0r[n], c0i = s_c0i[n];
        float c1r = s_c1r[n], c1i = s_c1i[n];
        #pragma unroll
        for (int j = 0; j < 8; j++) {
            k0a[j] += c0r * vr - c0i * vi;
            k1a[j] += c1r * vr - c1i * vi;
            float nvr = vr * sr - vi * si;
            float nvi = vr * si + vi * sr;
            vr = nvr; vi = nvi;
        }
    }
    #pragma unroll
    for (int j = 0; j < 8; j++) {
        g_K[(size_t)h * Ll + l0 + j]        = 2.0f * k0a[j];
        g_K[((size_t)Hh + h) * Ll + l0 + j] = 2.0f * k1a[j];
    }
}

// ---------------- conv helpers ----------------
__device__ __forceinline__ void load8(float (&d)[8], const float* p) {
    *(float4*)&d[0] = *(const float4*)&p[0];
    *(float4*)&d[4] = *(const float4*)&p[4];
}
// causal chunk: acc[j] += kk[tu] * w[8 + j - tu], w = concat(lo, mid, hi)
__device__ __forceinline__ void step_c(float (&acc)[16], const float* sk, int t0,
                                       const float (&lo)[8], const float (&mid)[8], const float (&hi)[8]) {
    float4 ka = *(const float4*)&sk[t0];
    float4 kb = *(const float4*)&sk[t0 + 4];
    float kk[8] = {ka.x, ka.y, ka.z, ka.w, kb.x, kb.y, kb.z, kb.w};
    #pragma unroll
    for (int tu = 0; tu < 8; tu++)
        #pragma unroll
        for (int j = 0; j < 16; j++) {
            int q = 8 + j - tu;
            float wv = (q < 8) ? lo[q] : ((q < 16) ? mid[q - 8] : hi[q - 16]);
            acc[j] += kk[tu] * wv;
        }
}
// anticausal chunk: acc[j] += kk[su] * w[1 + j + su]
__device__ __forceinline__ void step_a(float (&acc)[16], const float* sk, int s0,
                                       const float (&lo)[8], const float (&mid)[8], const float (&hi)[8]) {
    float4 ka = *(const float4*)&sk[s0];
    float4 kb = *(const float4*)&sk[s0 + 4];
    float kk[8] = {ka.x, ka.y, ka.z, ka.w, kb.x, kb.y, kb.z, kb.w};
    #pragma unroll
    for (int su = 0; su < 8; su++)
        #pragma unroll
        for (int j = 0; j < 16; j++) {
            int q = 1 + j + su;
            float wv = (q < 8) ? lo[q] : ((q < 16) ? mid[q - 8] : hi[q - 16]);
            acc[j] += kk[su] * wv;
        }
}

// ---------------- bidirectional conv + D*u + GELU (in-place on g_ut) ----------------
// 32 threads, 16 outputs each, rolling register window (2 new LDS.128 per 8-tap chunk).
__global__ void __launch_bounds__(32) conv_kernel(const float* __restrict__ Dvec) {
    int bx = blockIdx.x;
    int b = bx / Hh, h = bx - b * Hh;
    __shared__ __align__(16) float up[2048];   // zero-padded u: valid at [512,1024)
    __shared__ __align__(16) float sk0[512], sk1[512];
    int t = threadIdx.x;
    float* urow = g_ut + ((size_t)b * Hh + h) * Ll;
    const float* k0row = g_K + (size_t)h * Ll;
    const float* k1row = g_K + ((size_t)Hh + h) * Ll;

    float4 z4 = make_float4(0.f, 0.f, 0.f, 0.f);
    #pragma unroll
    for (int i = 0; i < 4; i++) {
        ((float4*)up)[t + 32 * i] = z4;                               // [0,512)
        ((float4*)up)[256 + t + 32 * i] = z4;                         // [1024,1536)
        ((float4*)up)[384 + t + 32 * i] = z4;                         // [1536,2048)
        ((float4*)up)[128 + t + 32 * i] = ((const float4*)urow)[t + 32 * i];
        ((float4*)sk0)[t + 32 * i] = ((const float4*)k0row)[t + 32 * i];
        ((float4*)sk1)[t + 32 * i] = ((const float4*)k1row)[t + 32 * i];
    }
    __syncthreads();

    int lb = t * 16;
    float acc[16];
    #pragma unroll
    for (int j = 0; j < 16; j++) acc[j] = 0.f;
    float A8[8], B8[8], C8[8];

    // causal: window base = 512 + lb - t0 - 8 (decreasing). lo gets new data.
    {
        const float* w0 = &up[512 + lb - 8];
        load8(A8, w0); load8(B8, w0 + 8); load8(C8, w0 + 16);
        step_c(acc, sk0, 0, A8, B8, C8);
        #pragma unroll 1
        for (int it = 0; it < 21; it++) {
            int t0 = it * 24;
            load8(C8, w0 - t0 - 8);
            step_c(acc, sk0, t0 + 8, C8, A8, B8);
            load8(B8, w0 - t0 - 16);
            step_c(acc, sk0, t0 + 16, B8, C8, A8);
            load8(A8, w0 - t0 - 24);
            step_c(acc, sk0, t0 + 24, A8, B8, C8);
        }
    }
    // anticausal: window base = 512 + lb + s0 (increasing). hi gets new data.
    {
        const float* v0 = &up[512 + lb];
        load8(A8, v0); load8(B8, v0 + 8); load8(C8, v0 + 16);
        step_a(acc, sk1, 0, A8, B8, C8);
        #pragma unroll 1
        for (int it = 0; it < 21; it++) {
            int s0 = it * 24;
            load8(A8, v0 + s0 + 24);
            step_a(acc, sk1, s0 + 8, B8, C8, A8);
            load8(B8, v0 + s0 + 32);
            step_a(acc, sk1, s0 + 16, C8, A8, B8);
            load8(C8, v0 + s0 + 40);
            step_a(acc, sk1, s0 + 24, A8, B8, C8);
        }
    }

    float dv = Dvec[h];
    float out[16];
    #pragma unroll
    for (int j = 0; j < 16; j++)
        out[j] = gelu_tanh(acc[j] + dv * up[512 + lb + j]);
    #pragma unroll
    for (int j = 0; j < 16; j += 4)
        *(float4*)&urow[lb + j] = *(float4*)&out[j];
}

// ---------------- transpose + bf16 hi/lo split: g_ut[B,H,L] -> g_yhi/g_ylo[B,L,H] ----------------
__global__ void cvty_kernel() {
    __shared__ float tile[32][33];
    int b  = blockIdx.z;
    int l0 = blockIdx.x * 32, h0 = blockIdx.y * 32;
    int tx = threadIdx.x, ty = threadIdx.y;
    #pragma unroll
    for (int k = 0; k < 4; k++) {
        int h = h0 + ty + k * 8;
        tile[ty + k * 8][tx] = g_ut[((size_t)b * Hh + h) * Ll + l0 + tx];
    }
    __syncthreads();
    #pragma unroll
    for (int k = 0; k < 4; k++) {
        int l = l0 + ty + k * 8;
        float v = tile[tx][ty + k * 8];
        __nv_bfloat16 hi = __float2bfloat16(v);
        __nv_bfloat16 lo = __float2bfloat16(v - __bfloat162float(hi));
        size_t idx = ((size_t)b * Ll + l) * Hh + h0 + tx;
        g_yhi[idx] = hi;
        g_ylo[idx] = lo;
    }
}

// ---------------- Wout fp32 -> bf16 hi/lo (all layers at once) ----------------
__global__ void cvtw_kernel(const float* __restrict__ Wout) {
    int i = blockIdx.x * 256 + threadIdx.x;
    float v = Wout[i];
    __nv_bfloat16 hi = __float2bfloat16(v);
    __nv_bfloat16 lo = __float2bfloat16(v - __bfloat162float(hi));
    g_whi[i] = hi;
    g_wlo[i] = lo;
}

// ---------------- mma.sync bf16x3 GEMM: z[m,o] = sum_h y[m,h]*W[o,h] + bout[o] ----------------
// CTA 128x128xK32, 4 warps (2x2) each 64x64, double-buffered cp.async.
// smem per stage: Ahi, Alo, Bhi, Blo each 128 rows x 80B (32 bf16 + 8 pad).
#define GST 40960          // stage bytes
#define GARR 10240         // array bytes
__device__ __forceinline__ void gemm_issue(uint32_t sbase, int m0, int o0, int k0,
                                           const __nv_bfloat16* whi_l, const __nv_bfloat16* wlo_l,
                                           int tid) {
    int r = tid >> 2, c = tid & 3;
    #pragma unroll
    for (int p = 0; p < 4; p++) {
        int row = r + p * 32;
        uint32_t so = (uint32_t)(row * 80 + c * 16);
        size_t ey = (size_t)(m0 + row) * Hh + k0 + c * 8;
        size_t ew = (size_t)(o0 + row) * Hh + k0 + c * 8;
        cp16(sbase + so,             g_yhi + ey);
        cp16(sbase + GARR + so,      g_ylo + ey);
        cp16(sbase + 2 * GARR + so,  whi_l + ew);
        cp16(sbase + 3 * GARR + so,  wlo_l + ew);
    }
}

__global__ void __launch_bounds__(128) gemm_mma_kernel(const __nv_bfloat16* __restrict__ whi_l,
                                                       const __nv_bfloat16* __restrict__ wlo_l,
                                                       const float* __restrict__ bout) {
    extern __shared__ __align__(16) char sm[];
    uint32_t s0 = smem_u32(sm);
    int tid = threadIdx.x, lane = tid & 31, wid = tid >> 5;
    int wm = wid & 1, wn = wid >> 1;          // 2 x 2 warps
    int m0 = blockIdx.y * 128, o0 = blockIdx.x * 128;

    float acc[4][8][4];
    #pragma unroll
    for (int i = 0; i < 4; i++)
        #pragma unroll
        for (int j = 0; j < 8; j++)
            #pragma unroll
            for (int q = 0; q < 4; q++) acc[i][j][q] = 0.f;

    gemm_issue(s0, m0, o0, 0, whi_l, wlo_l, tid);
    cp_commit();

    const int NCH = Hh / 32;   // 24
    for (int c = 0; c < NCH; c++) {
        int st = c & 1;
        if (c + 1 < NCH) {
            gemm_issue(s0 + (st ^ 1) * GST, m0, o0, (c + 1) * 32, whi_l, wlo_l, tid);
            cp_commit();
            cp_wait1();
        } else {
            cp_wait0();
        }
        __syncthreads();

        uint32_t sA = s0 + st * GST;
        uint32_t sB = sA + 2 * GARR;
        #pragma unroll
        for (int ks = 0; ks < 2; ks++) {
            uint32_t abase = sA + (uint32_t)((lane & 15) * 80 + ks * 32 + (lane >> 4) * 16);
            uint32_t ahi[4][4], alo[4][4];
            #pragma unroll
            for (int mf = 0; mf < 4; mf++) {
                uint32_t ad = abase + (uint32_t)((wm * 64 + mf * 16) * 80);
                ldmx4(ahi[mf], ad);
                ldmx4(alo[mf], ad + GARR);
            }
            #pragma unroll
            for (int ng = 0; ng < 4; ng++) {
                int nrow = wn * 64 + ng * 16 + (lane & 7) + ((lane >> 4) & 1) * 8;
                uint32_t bd = sB + (uint32_t)(nrow * 80 + ks * 32 + ((lane >> 3) & 1) * 16);
                uint32_t bh[4], bl[4];
                ldmx4(bh, bd);
                ldmx4(bl, bd + GARR);
                #pragma unroll
                for (int mf = 0; mf < 4; mf++) {
                    mma_bf16(acc[mf][ng * 2],     ahi[mf], bh[0], bh[1]);
                    mma_bf16(acc[mf][ng * 2 + 1], ahi[mf], bh[2], bh[3]);
                    mma_bf16(acc[mf][ng * 2],     ahi[mf], bl[0], bl[1]);
                    mma_bf16(acc[mf][ng * 2 + 1], ahi[mf], bl[2], bl[3]);
                    mma_bf16(acc[mf][ng * 2],     alo[mf], bh[0], bh[1]);
                    mma_bf16(acc[mf][ng * 2 + 1], alo[mf], bh[2], bh[3]);
                }
            }
        }
        __syncthreads();
    }

    // epilogue: direct f32 stores + bias
    #pragma unroll
    for (int mf = 0; mf < 4; mf++) {
        int mrow = m0 + wm * 64 + mf * 16 + (lane >> 2);
        #pragma unroll
        for (int nf = 0; nf < 8; nf++) {
            int ncol = o0 + wn * 64 + nf * 8 + (lane & 3) * 2;
            float b0 = bout[ncol], b1 = bout[ncol + 1];
            float* z0 = g_z + (size_t)mrow * Hh + ncol;
            float* z1 = g_z + (size_t)(mrow + 8) * Hh + ncol;
            *(float2*)z0 = make_float2(acc[mf][nf][0] + b0, acc[mf][nf][1] + b1);
            *(float2*)z1 = make_float2(acc[mf][nf][2] + b0, acc[mf][nf][3] + b1);
        }
    }
}

// ---------------- LN2 + residual: x += LN(z) ----------------
__global__ void ln2res_kernel(const float* __restrict__ w,
                              const float* __restrict__ bsh,
                              float* __restrict__ x) {
    int row = blockIdx.x;
    const float* zr = g_z + (size_t)row * Hh;
    float v[3];
    float s = 0.f, ss = 0.f;
    #pragma unroll
    for (int q = 0; q < 3; q++) {
        v[q] = zr[threadIdx.x + q * 256];
        s += v[q]; ss += v[q] * v[q];
    }
    for (int o = 16; o; o >>= 1) {
        s  += __shfl_down_sync(0xffffffffu, s, o);
        ss += __shfl_down_sync(0xffffffffu, ss, o);
    }
    __shared__ float s1[8], s2[8];
    __shared__ float smu, srs;
    int wi = threadIdx.x >> 5;
    if ((threadIdx.x & 31) == 0) { s1[wi] = s; s2[wi] = ss; }
    __syncthreads();
    if (threadIdx.x == 0) {
        float S = 0.f, SS = 0.f;
        #pragma unroll
        for (int k = 0; k < 8; k++) { S += s1[k]; SS += s2[k]; }
        float mu = S / Hh;
        float var = SS / Hh - mu * mu;
        smu = mu;
        srs = rsqrtf(var + 1e-5f);
    }
    __syncthreads();
    float mu = smu, rs = srs;
    #pragma unroll
    for (int q = 0; q < 3; q++) {
        int j = threadIdx.x + q * 256;
        size_t idx = (size_t)row * Hh + j;
        x[idx] = x[idx] + ((v[q] - mu) * rs * w[j] + bsh[j]);
    }
}

// ---------------- launch ----------------
extern "C" void kernel_launch(void* const* d_in, const int* in_sizes, int n_in,
                              void* d_out, int out_size) {
    const float* x_in   = (const float*)d_in[0];
    const int*   mask   = (const int*)  d_in[1];
    const float* ln1_w  = (const float*)d_in[2];
    const float* ln1_b  = (const float*)d_in[3];
    const float* log_dt = (const float*)d_in[4];
    const float* A_re   = (const float*)d_in[5];
    const float* A_im   = (const float*)d_in[6];
    const float* C_re   = (const float*)d_in[7];
    const float* C_im   = (const float*)d_in[8];
    const float* Dv     = (const float*)d_in[9];
    const float* Wout   = (const float*)d_in[10];
    const float* bout   = (const float*)d_in[11];
    const float* ln2_w  = (const float*)d_in[12];
    const float* ln2_b  = (const float*)d_in[13];
    float* x = (float*)d_out;

    static bool attr_set = false;
    if (!attr_set) {
        cudaFuncSetAttribute(gemm_mma_kernel, cudaFuncAttributeMaxDynamicSharedMemorySize, 2 * GST);
        attr_set = true;
    }

    cudaMemcpyAsync(x, x_in, sizeof(float) * (size_t)Bb * Ll * Hh,
                    cudaMemcpyDeviceToDevice, 0);
    cvtw_kernel<<<NLl * Hh * Hh / 256, 256>>>(Wout);

    __nv_bfloat16* whi_base;
    __nv_bfloat16* wlo_base;
    cudaGetSymbolAddress((void**)&whi_base, g_whi);
    cudaGetSymbolAddress((void**)&wlo_base, g_wlo);

    for (int i = 0; i < NLl; i++) {
        kcomp_kernel<<<Hh, 64>>>(i, log_dt, A_re, A_im, C_re, C_im);
        rowstats_kernel<<<Bb * Ll, 256>>>(x);
        ln1t_kernel<<<dim3(Ll / 32, Hh / 32, Bb), dim3(32, 8)>>>(
            x, ln1_w + i * Hh, ln1_b + i * Hh, mask);
        conv_kernel<<<Bb * Hh, 32>>>(Dv + i * Hh);
        cvty_kernel<<<dim3(Ll / 32, Hh / 32, Bb), dim3(32, 8)>>>();
        gemm_mma_kernel<<<dim3(Hh / 128, Bb * Ll / 128), 128, 2 * GST>>>(
            whi_base + (size_t)i * Hh * Hh, wlo_base + (size_t)i * Hh * Hh, bout + i * Hh);
        ln2res_kernel<<<Bb * Ll, 256>>>(ln2_w + i * Hh, ln2_b + i * Hh, x);
    }
}

// round 5
// speedup vs baseline: 10.0178x; 2.7143x over previous
#include <cuda_runtime.h>
#include <cuda_fp16.h>
#include <math.h>
#include <stdint.h>

#define Bb 32
#define Ll 512
#define Hh 768
#define Nn 64
#define NLl 4

// ---------------- device scratch ----------------
__device__ __align__(16) float g_ut[(size_t)Bb * Hh * Ll];   // masked LN1 output [B,H,L]
__device__ __align__(16) float g_z[(size_t)Bb * Ll * Hh];    // conv scratch [B,H,L], later GEMM out [B,L,H]
__device__ __align__(16) float g_K[2 * Hh * Ll];             // conv kernels [2,H,L]
__device__ float g_mu[Bb * Ll];
__device__ float g_rs[Bb * Ll];
__device__ __align__(16) half g_yh[(size_t)Bb * Ll * Hh];    // y fp16 [B,L,H]
__device__ __align__(16) half g_wh[(size_t)NLl * Hh * Hh];   // W fp16

__device__ __forceinline__ float gelu_tanh(float x) {
    float x3 = x * x * x;
    return 0.5f * x * (1.0f + tanhf(0.7978845608028654f * (x + 0.044715f * x3)));
}
__device__ __forceinline__ uint32_t smem_u32(const void* p) {
    uint32_t a;
    asm("{ .reg .u64 t; cvta.to.shared.u64 t, %1; cvt.u32.u64 %0, t; }" : "=r"(a) : "l"(p));
    return a;
}
__device__ __forceinline__ void cp16(uint32_t saddr, const void* g) {
    asm volatile("cp.async.ca.shared.global [%0], [%1], 16;" :: "r"(saddr), "l"(g) : "memory");
}
__device__ __forceinline__ void cp_commit() { asm volatile("cp.async.commit_group;" ::: "memory"); }
__device__ __forceinline__ void cp_wait1()  { asm volatile("cp.async.wait_group 1;" ::: "memory"); }
__device__ __forceinline__ void cp_wait0()  { asm volatile("cp.async.wait_group 0;" ::: "memory"); }
__device__ __forceinline__ void ldmx4(uint32_t* r, uint32_t addr) {
    asm volatile("ldmatrix.sync.aligned.m8n8.x4.shared.b16 {%0,%1,%2,%3}, [%4];"
        : "=r"(r[0]), "=r"(r[1]), "=r"(r[2]), "=r"(r[3]) : "r"(addr));
}
__device__ __forceinline__ void mma_f16(float* c, const uint32_t* a, uint32_t b0, uint32_t b1) {
    asm volatile("mma.sync.aligned.m16n8k16.row.col.f32.f16.f16.f32 "
        "{%0,%1,%2,%3}, {%4,%5,%6,%7}, {%8,%9}, {%0,%1,%2,%3};"
        : "+f"(c[0]), "+f"(c[1]), "+f"(c[2]), "+f"(c[3])
        : "r"(a[0]), "r"(a[1]), "r"(a[2]), "r"(a[3]), "r"(b0), "r"(b1));
}

// ---------------- LN row statistics (layer 0 only) ----------------
__global__ void rowstats_kernel(const float* __restrict__ x) {
    int row = blockIdx.x;
    const float* xr = x + (size_t)row * Hh;
    float s = 0.f, ss = 0.f;
    for (int j = threadIdx.x; j < Hh; j += 256) {
        float v = xr[j];
        s += v; ss += v * v;
    }
    for (int o = 16; o; o >>= 1) {
        s  += __shfl_down_sync(0xffffffffu, s, o);
        ss += __shfl_down_sync(0xffffffffu, ss, o);
    }
    __shared__ float s1[8], s2[8];
    int w = threadIdx.x >> 5;
    if ((threadIdx.x & 31) == 0) { s1[w] = s; s2[w] = ss; }
    __syncthreads();
    if (threadIdx.x == 0) {
        float S = 0.f, SS = 0.f;
        #pragma unroll
        for (int k = 0; k < 8; k++) { S += s1[k]; SS += s2[k]; }
        float mu = S / Hh;
        float var = SS / Hh - mu * mu;
        g_mu[row] = mu;
        g_rs[row] = rsqrtf(var + 1e-5f);
    }
}

// ---------------- LN1 apply + mask + transpose to [B,H,L] ----------------
__global__ void ln1t_kernel(const float* __restrict__ x,
                            const float* __restrict__ w,
                            const float* __restrict__ bsh,
                            const int* __restrict__ mask) {
    __shared__ float tile[32][33];
    int b  = blockIdx.z;
    int l0 = blockIdx.x * 32, h0 = blockIdx.y * 32;
    int tx = threadIdx.x, ty = threadIdx.y;
    float wv = w[h0 + tx], bv = bsh[h0 + tx];
    #pragma unroll
    for (int k = 0; k < 4; k++) {
        int l   = l0 + ty + k * 8;
        int row = b * Ll + l;
        float v  = x[(size_t)row * Hh + h0 + tx];
        float mf = (float)mask[row];
        tile[ty + k * 8][tx] = ((v - g_mu[row]) * g_rs[row] * wv + bv) * mf;
    }
    __syncthreads();
    #pragma unroll
    for (int k = 0; k < 4; k++) {
        int h = h0 + ty + k * 8;
        g_ut[((size_t)b * Hh + h) * Ll + l0 + tx] = tile[tx][ty + k * 8];
    }
}

// ---------------- S4D kernel K[2,H,L] precompute ----------------
__global__ void __launch_bounds__(64) kcomp_kernel(int layer,
                             const float* __restrict__ log_dt,
                             const float* __restrict__ A_re,
                             const float* __restrict__ A_im,
                             const float* __restrict__ C_re,
                             const float* __restrict__ C_im) {
    int h = blockIdx.x;
    __shared__ float s_ar[Nn], s_ai[Nn];
    __shared__ float s_sr[Nn], s_si[Nn];
    __shared__ float s_c0r[Nn], s_c0i[Nn], s_c1r[Nn], s_c1i[Nn];
    int t = threadIdx.x;
    {
        float dt = expf(log_dt[layer * Hh + h]);
        float Ar = -expf(A_re[((size_t)layer * Hh + h) * Nn + t]);
        float Ai = A_im[((size_t)layer * Hh + h) * Nn + t];
        float ar = dt * Ar, ai = dt * Ai;
        float er = expf(ar), sn, cs;
        sincosf(ai, &sn, &cs);
        float zr = er * cs - 1.0f, zi = er * sn;
        float den = Ar * Ar + Ai * Ai;
        float wr = (zr * Ar + zi * Ai) / den;
        float wi = (zi * Ar - zr * Ai) / den;
        size_t c0 = ((size_t)(layer * 2 + 0) * Hh + h) * Nn + t;
        size_t c1 = ((size_t)(layer * 2 + 1) * Hh + h) * Nn + t;
        float cr0 = C_re[c0], ci0 = C_im[c0];
        float cr1 = C_re[c1], ci1 = C_im[c1];
        s_ar[t] = ar; s_ai[t] = ai;
        s_sr[t] = er * cs; s_si[t] = er * sn;
        s_c0r[t] = cr0 * wr - ci0 * wi;  s_c0i[t] = cr0 * wi + ci0 * wr;
        s_c1r[t] = cr1 * wr - ci1 * wi;  s_c1i[t] = cr1 * wi + ci1 * wr;
    }
    __syncthreads();

    int l0 = t * 8;
    float fl0 = (float)l0;
    float k0a[8], k1a[8];
    #pragma unroll
    for (int j = 0; j < 8; j++) { k0a[j] = 0.f; k1a[j] = 0.f; }

    for (int n = 0; n < Nn; n++) {
        float ar = s_ar[n], ai = s_ai[n];
        float e0 = expf(ar * fl0);
        float sn, cs;
        sincosf(ai * fl0, &sn, &cs);
        float vr = e0 * cs, vi = e0 * sn;
        float sr = s_sr[n], si = s_si[n];
        float c0r = s_c0r[n], c0i = s_c0i[n];
        float c1r = s_c1r[n], c1i = s_c1i[n];
        #pragma unroll
        for (int j = 0; j < 8; j++) {
            k0a[j] += c0r * vr - c0i * vi;
            k1a[j] += c1r * vr - c1i * vi;
            float nvr = vr * sr - vi * si;
            float nvi = vr * si + vi * sr;
            vr = nvr; vi = nvi;
        }
    }
    #pragma unroll
    for (int j = 0; j < 8; j++) {
        g_K[(size_t)h * Ll + l0 + j]        = 2.0f * k0a[j];
        g_K[((size_t)Hh + h) * Ll + l0 + j] = 2.0f * k1a[j];
    }
}

// ---------------- conv via block-Toeplitz mma.sync fp16 ----------------
// y[l] = sum_j c[j-l] u[j]; c[dd<=0] = k0[-dd], c[dd>=1] = k1[dd-1].
// M_d[p][q] = c[64(d-8)+q-p]; Y_i = sum_d M_d @ U_{i+d-8}, 0<=i+d-8<8.
// CTA = (h, 16-batch half), 8 warps; warp i owns Y_i [64 x 16].
#define USTRIDE 520          // halves per us row (512 + 8 pad)
#define MSTRIDE 72           // halves per M row (64 + 8 pad)
#define OFF_US 0             // 16 * 520 * 2  = 16640
#define OFF_CS 16640         // 1152 * 4      = 4608
#define OFF_M  21248         // 2 * 64*72*2   = 18432 -> 39680
#define CONV_SMEM 39936      // Ys overlays from 0: 512*18*4 = 36864

__device__ __forceinline__ void build_M(half* Mdst, const float* cs, int d, int t) {
    int p = t & 63, q0 = (t >> 6) * 16;
    int base = 576 + 64 * (d - 8) + q0 - p;
    half2 tmp[8];
    #pragma unroll
    for (int j = 0; j < 8; j++)
        tmp[j] = __floats2half2_rn(cs[base + 2 * j], cs[base + 2 * j + 1]);
    half2* dst = (half2*)(Mdst + p * MSTRIDE + q0);
    #pragma unroll
    for (int j = 0; j < 8; j++) dst[j] = tmp[j];
}

__global__ void __launch_bounds__(256) conv_tc_kernel() {
    extern __shared__ __align__(16) char sm[];
    half*  us = (half*)(sm + OFF_US);
    float* cs = (float*)(sm + OFF_CS);
    half*  M0 = (half*)(sm + OFF_M);
    half*  M1 = (half*)(sm + OFF_M + 9216);
    float* Ys = (float*)sm;
    uint32_t us_a = smem_u32(us);
    uint32_t m_a  = smem_u32(M0);

    int t = threadIdx.x, lane = t & 31, wid = t >> 5;
    int h = blockIdx.x >> 1, bh = (blockIdx.x & 1) * 16;

    // load u (16 batch rows) -> fp16
    {
        int row = t >> 4, c0 = (t & 15) * 32;
        const float* ur = g_ut + ((size_t)(bh + row) * Hh + h) * Ll + c0;
        half2* dst = (half2*)(us + row * USTRIDE + c0);
        #pragma unroll
        for (int j = 0; j < 8; j++) {
            float4 v = ((const float4*)ur)[j];
            dst[j * 2]     = __floats2half2_rn(v.x, v.y);
            dst[j * 2 + 1] = __floats2half2_rn(v.z, v.w);
        }
    }
    // build c array: cs[576+dd]
    {
        const float* k0r = g_K + (size_t)h * Ll;
        const float* k1r = g_K + ((size_t)Hh + h) * Ll;
        float2 a = ((const float2*)k0r)[t];
        float2 b = ((const float2*)k1r)[t];
        cs[576 - 2 * t] = a.x;  cs[575 - 2 * t] = a.y;
        cs[577 + 2 * t] = b.x;  cs[578 + 2 * t] = b.y;
    }
    __syncthreads();

    float acc[4][2][4];
    #pragma unroll
    for (int i = 0; i < 4; i++)
        #pragma unroll
        for (int j = 0; j < 2; j++)
            #pragma unroll
            for (int q = 0; q < 4; q++) acc[i][j][q] = 0.f;

    build_M(M1, cs, 1, t);
    __syncthreads();

    for (int d = 1; d <= 15; d++) {
        if (d < 15) build_M((d & 1) ? M0 : M1, cs, d + 1, t);   // buf[(d+1)&1]
        int jb = wid + d - 8;
        if (jb >= 0 && jb < 8) {
            uint32_t ma = m_a + ((d & 1) ? 9216u : 0u);
            #pragma unroll
            for (int ks = 0; ks < 4; ks++) {
                uint32_t ar[4][4];
                uint32_t abase = ma + (uint32_t)((lane & 15) * 144 + ks * 32 + (lane >> 4) * 16);
                #pragma unroll
                for (int mf = 0; mf < 4; mf++)
                    ldmx4(ar[mf], abase + (uint32_t)(mf * 16 * 144));
                int nrow = (lane & 7) + ((lane >> 4) & 1) * 8;
                uint32_t bd = us_a + (uint32_t)(nrow * 1040 + jb * 128 + ks * 32 + ((lane >> 3) & 1) * 16);
                uint32_t br[4];
                ldmx4(br, bd);
                #pragma unroll
                for (int mf = 0; mf < 4; mf++) {
                    mma_f16(acc[mf][0], ar[mf], br[0], br[1]);
                    mma_f16(acc[mf][1], ar[mf], br[2], br[3]);
                }
            }
        }
        __syncthreads();
    }

    // stage Y to smem [l][b], stride 18
    #pragma unroll
    for (int mf = 0; mf < 4; mf++) {
        int l = wid * 64 + mf * 16 + (lane >> 2);
        #pragma unroll
        for (int nf = 0; nf < 2; nf++) {
            int b = nf * 8 + (lane & 3) * 2;
            *(float2*)&Ys[l * 18 + b]       = make_float2(acc[mf][nf][0], acc[mf][nf][1]);
            *(float2*)&Ys[(l + 8) * 18 + b] = make_float2(acc[mf][nf][2], acc[mf][nf][3]);
        }
    }
    __syncthreads();

    // coalesced write to g_z [B,H,L]
    int l4 = (t & 127) * 4;
    #pragma unroll
    for (int pass = 0; pass < 8; pass++) {
        int b = pass * 2 + (t >> 7);
        float4 v;
        v.x = Ys[(l4 + 0) * 18 + b];
        v.y = Ys[(l4 + 1) * 18 + b];
        v.z = Ys[(l4 + 2) * 18 + b];
        v.w = Ys[(l4 + 3) * 18 + b];
        *(float4*)&g_z[((size_t)(bh + b) * Hh + h) * Ll + l4] = v;
    }
}

// ---------------- D*u + GELU + transpose + fp16: -> g_yh [B,L,H] ----------------
__global__ void cvty_kernel(const float* __restrict__ Dvec) {
    __shared__ float tile[32][33];
    int b  = blockIdx.z;
    int l0 = blockIdx.x * 32, h0 = blockIdx.y * 32;
    int tx = threadIdx.x, ty = threadIdx.y;
    #pragma unroll
    for (int k = 0; k < 4; k++) {
        int h = h0 + ty + k * 8;
        size_t idx = ((size_t)b * Hh + h) * Ll + l0 + tx;
        float cv = g_z[idx];
        float u  = g_ut[idx];
        tile[ty + k * 8][tx] = gelu_tanh(cv + Dvec[h] * u);
    }
    __syncthreads();
    #pragma unroll
    for (int k = 0; k < 4; k++) {
        int l = l0 + ty + k * 8;
        g_yh[((size_t)b * Ll + l) * Hh + h0 + tx] = __float2half_rn(tile[tx][ty + k * 8]);
    }
}

// ---------------- Wout fp32 -> fp16 (all layers once) ----------------
__global__ void cvtw_kernel(const float* __restrict__ Wout) {
    int i = blockIdx.x * 256 + threadIdx.x;
    g_wh[i] = __float2half_rn(Wout[i]);
}

// ---------------- mma.sync fp16 GEMM: z[m,o] = sum_h y[m,h]*W[o,h] + bout[o] ----------------
#define GST2 20480
#define GARR2 10240
__device__ __forceinline__ void gemm_issue16(uint32_t sbase, int m0, int o0, int k0,
                                             const half* wl, int tid) {
    int r = tid >> 2, c = tid & 3;
    #pragma unroll
    for (int p = 0; p < 4; p++) {
        int row = r + p * 32;
        uint32_t so = (uint32_t)(row * 80 + c * 16);
        cp16(sbase + so,         g_yh + (size_t)(m0 + row) * Hh + k0 + c * 8);
        cp16(sbase + GARR2 + so, wl   + (size_t)(o0 + row) * Hh + k0 + c * 8);
    }
}

__global__ void __launch_bounds__(128) gemm_mma_kernel(const half* __restrict__ wl,
                                                       const float* __restrict__ bout) {
    extern __shared__ __align__(16) char sm[];
    uint32_t s0 = smem_u32(sm);
    int tid = threadIdx.x, lane = tid & 31, wid = tid >> 5;
    int wm = wid & 1, wn = wid >> 1;
    int m0 = blockIdx.y * 128, o0 = blockIdx.x * 128;

    float acc[4][8][4];
    #pragma unroll
    for (int i = 0; i < 4; i++)
        #pragma unroll
        for (int j = 0; j < 8; j++)
            #pragma unroll
            for (int q = 0; q < 4; q++) acc[i][j][q] = 0.f;

    gemm_issue16(s0, m0, o0, 0, wl, tid);
    cp_commit();

    const int NCH = Hh / 32;   // 24
    for (int c = 0; c < NCH; c++) {
        int st = c & 1;
        if (c + 1 < NCH) {
            gemm_issue16(s0 + (st ^ 1) * GST2, m0, o0, (c + 1) * 32, wl, tid);
            cp_commit();
            cp_wait1();
        } else {
            cp_wait0();
        }
        __syncthreads();

        uint32_t sA = s0 + st * GST2;
        uint32_t sB = sA + GARR2;
        #pragma unroll
        for (int ks = 0; ks < 2; ks++) {
            uint32_t abase = sA + (uint32_t)((lane & 15) * 80 + ks * 32 + (lane >> 4) * 16);
            uint32_t a[4][4];
            #pragma unroll
            for (int mf = 0; mf < 4; mf++)
                ldmx4(a[mf], abase + (uint32_t)((wm * 64 + mf * 16) * 80));
            #pragma unroll
            for (int ng = 0; ng < 4; ng++) {
                int nrow = wn * 64 + ng * 16 + (lane & 7) + ((lane >> 4) & 1) * 8;
                uint32_t bd = sB + (uint32_t)(nrow * 80 + ks * 32 + ((lane >> 3) & 1) * 16);
                uint32_t bh[4];
                ldmx4(bh, bd);
                #pragma unroll
                for (int mf = 0; mf < 4; mf++) {
                    mma_f16(acc[mf][ng * 2],     a[mf], bh[0], bh[1]);
                    mma_f16(acc[mf][ng * 2 + 1], a[mf], bh[2], bh[3]);
                }
            }
        }
        __syncthreads();
    }

    #pragma unroll
    for (int mf = 0; mf < 4; mf++) {
        int mrow = m0 + wm * 64 + mf * 16 + (lane >> 2);
        #pragma unroll
        for (int nf = 0; nf < 8; nf++) {
            int ncol = o0 + wn * 64 + nf * 8 + (lane & 3) * 2;
            float b0 = bout[ncol], b1 = bout[ncol + 1];
            float* z0 = g_z + (size_t)mrow * Hh + ncol;
            float* z1 = g_z + (size_t)(mrow + 8) * Hh + ncol;
            *(float2*)z0 = make_float2(acc[mf][nf][0] + b0, acc[mf][nf][1] + b1);
            *(float2*)z1 = make_float2(acc[mf][nf][2] + b0, acc[mf][nf][3] + b1);
        }
    }
}

// ---------------- LN2 + residual + next-layer row stats ----------------
__global__ void ln2res_kernel(const float* __restrict__ w,
                              const float* __restrict__ bsh,
                              float* __restrict__ x) {
    int row = blockIdx.x;
    const float* zr = g_z + (size_t)row * Hh;
    float v[3];
    float s = 0.f, ss = 0.f;
    #pragma unroll
    for (int q = 0; q < 3; q++) {
        v[q] = zr[threadIdx.x + q * 256];
        s += v[q]; ss += v[q] * v[q];
    }
    for (int o = 16; o; o >>= 1) {
        s  += __shfl_down_sync(0xffffffffu, s, o);
        ss += __shfl_down_sync(0xffffffffu, ss, o);
    }
    __shared__ float s1[8], s2[8];
    __shared__ float smu, srs;
    int wi = threadIdx.x >> 5;
    if ((threadIdx.x & 31) == 0) { s1[wi] = s; s2[wi] = ss; }
    __syncthreads();
    if (threadIdx.x == 0) {
        float S = 0.f, SS = 0.f;
        #pragma unroll
        for (int k = 0; k < 8; k++) { S += s1[k]; SS += s2[k]; }
        float mu = S / Hh;
        float var = SS / Hh - mu * mu;
        smu = mu;
        srs = rsqrtf(var + 1e-5f);
    }
    __syncthreads();
    float mu = smu, rs = srs;
    float xn[3];
    float s2n = 0.f, ss2n = 0.f;
    #pragma unroll
    for (int q = 0; q < 3; q++) {
        int j = threadIdx.x + q * 256;
        size_t idx = (size_t)row * Hh + j;
        xn[q] = x[idx] + ((v[q] - mu) * rs * w[j] + bsh[j]);
        x[idx] = xn[q];
        s2n += xn[q]; ss2n += xn[q] * xn[q];
    }
    // next-layer stats
    for (int o = 16; o; o >>= 1) {
        s2n  += __shfl_down_sync(0xffffffffu, s2n, o);
        ss2n += __shfl_down_sync(0xffffffffu, ss2n, o);
    }
    __syncthreads();
    if ((threadIdx.x & 31) == 0) { s1[wi] = s2n; s2[wi] = ss2n; }
    __syncthreads();
    if (threadIdx.x == 0) {
        float S = 0.f, SS = 0.f;
        #pragma unroll
        for (int k = 0; k < 8; k++) { S += s1[k]; SS += s2[k]; }
        float mun = S / Hh;
        float varn = SS / Hh - mun * mun;
        g_mu[row] = mun;
        g_rs[row] = rsqrtf(varn + 1e-5f);
    }
}

// ---------------- launch ----------------
extern "C" void kernel_launch(void* const* d_in, const int* in_sizes, int n_in,
                              void* d_out, int out_size) {
    const float* x_in   = (const float*)d_in[0];
    const int*   mask   = (const int*)  d_in[1];
    const float* ln1_w  = (const float*)d_in[2];
    const float* ln1_b  = (const float*)d_in[3];
    const float* log_dt = (const float*)d_in[4];
    const float* A_re   = (const float*)d_in[5];
    const float* A_im   = (const float*)d_in[6];
    const float* C_re   = (const float*)d_in[7];
    const float* C_im   = (const float*)d_in[8];
    const float* Dv     = (const float*)d_in[9];
    const float* Wout   = (const float*)d_in[10];
    const float* bout   = (const float*)d_in[11];
    const float* ln2_w  = (const float*)d_in[12];
    const float* ln2_b  = (const float*)d_in[13];
    float* x = (float*)d_out;

    cudaMemcpyAsync(x, x_in, sizeof(float) * (size_t)Bb * Ll * Hh,
                    cudaMemcpyDeviceToDevice, 0);
    cvtw_kernel<<<NLl * Hh * Hh / 256, 256>>>(Wout);
    rowstats_kernel<<<Bb * Ll, 256>>>(x);

    half* wh_base;
    cudaGetSymbolAddress((void**)&wh_base, g_wh);

    for (int i = 0; i < NLl; i++) {
        kcomp_kernel<<<Hh, 64>>>(i, log_dt, A_re, A_im, C_re, C_im);
        ln1t_kernel<<<dim3(Ll / 32, Hh / 32, Bb), dim3(32, 8)>>>(
            x, ln1_w + i * Hh, ln1_b + i * Hh, mask);
        conv_tc_kernel<<<Hh * 2, 256, CONV_SMEM>>>();
        cvty_kernel<<<dim3(Ll / 32, Hh / 32, Bb), dim3(32, 8)>>>(Dv + i * Hh);
        gemm_mma_kernel<<<dim3(Hh / 128, Bb * Ll / 128), 128, 2 * GST2>>>(
            wh_base + (size_t)i * Hh * Hh, bout + i * Hh);
        ln2res_kernel<<<Bb * Ll, 256>>>(ln2_w + i * Hh, ln2_b + i * Hh, x);
    }
}

// round 6
// speedup vs baseline: 12.4364x; 1.2414x over previous
#include <cuda_runtime.h>
#include <cuda_fp16.h>
#include <math.h>
#include <stdint.h>

#define Bb 32
#define Ll 512
#define Hh 768
#define Nn 64
#define NLl 4

// ---------------- device scratch ----------------
__device__ __align__(16) half  g_uh[(size_t)Bb * Hh * Ll];   // LN1 out fp16 [B,H,L]; conv overwrites in-place with gelu(conv+Du)
__device__ __align__(16) float g_z[(size_t)Bb * Ll * Hh];    // GEMM output [B,L,H]
__device__ __align__(16) float g_K[2 * Hh * Ll];             // conv kernels [2,H,L]
__device__ float g_mu[Bb * Ll];
__device__ float g_rs[Bb * Ll];
__device__ __align__(16) half g_wh[(size_t)NLl * Hh * Hh];   // W fp16

__device__ __forceinline__ float gelu_tanh(float x) {
    float x3 = x * x * x;
    return 0.5f * x * (1.0f + tanhf(0.7978845608028654f * (x + 0.044715f * x3)));
}
__device__ __forceinline__ uint32_t smem_u32(const void* p) {
    uint32_t a;
    asm("{ .reg .u64 t; cvta.to.shared.u64 t, %1; cvt.u32.u64 %0, t; }" : "=r"(a) : "l"(p));
    return a;
}
__device__ __forceinline__ void cp16(uint32_t saddr, const void* g) {
    asm volatile("cp.async.ca.shared.global [%0], [%1], 16;" :: "r"(saddr), "l"(g) : "memory");
}
__device__ __forceinline__ void cp_commit() { asm volatile("cp.async.commit_group;" ::: "memory"); }
__device__ __forceinline__ void cp_wait1()  { asm volatile("cp.async.wait_group 1;" ::: "memory"); }
__device__ __forceinline__ void cp_wait0()  { asm volatile("cp.async.wait_group 0;" ::: "memory"); }
__device__ __forceinline__ void ldmx4(uint32_t* r, uint32_t addr) {
    asm volatile("ldmatrix.sync.aligned.m8n8.x4.shared.b16 {%0,%1,%2,%3}, [%4];"
        : "=r"(r[0]), "=r"(r[1]), "=r"(r[2]), "=r"(r[3]) : "r"(addr));
}
__device__ __forceinline__ void ldmx4t(uint32_t* r, uint32_t addr) {
    asm volatile("ldmatrix.sync.aligned.m8n8.x4.trans.shared.b16 {%0,%1,%2,%3}, [%4];"
        : "=r"(r[0]), "=r"(r[1]), "=r"(r[2]), "=r"(r[3]) : "r"(addr));
}
__device__ __forceinline__ void mma_f16(float* c, const uint32_t* a, uint32_t b0, uint32_t b1) {
    asm volatile("mma.sync.aligned.m16n8k16.row.col.f32.f16.f16.f32 "
        "{%0,%1,%2,%3}, {%4,%5,%6,%7}, {%8,%9}, {%0,%1,%2,%3};"
        : "+f"(c[0]), "+f"(c[1]), "+f"(c[2]), "+f"(c[3])
        : "r"(a[0]), "r"(a[1]), "r"(a[2]), "r"(a[3]), "r"(b0), "r"(b1));
}

// ---------------- LN row statistics (layer 0 only) ----------------
__global__ void rowstats_kernel(const float* __restrict__ x) {
    int row = blockIdx.x;
    const float* xr = x + (size_t)row * Hh;
    float s = 0.f, ss = 0.f;
    for (int j = threadIdx.x; j < Hh; j += 256) {
        float v = xr[j];
        s += v; ss += v * v;
    }
    for (int o = 16; o; o >>= 1) {
        s  += __shfl_down_sync(0xffffffffu, s, o);
        ss += __shfl_down_sync(0xffffffffu, ss, o);
    }
    __shared__ float s1[8], s2[8];
    int w = threadIdx.x >> 5;
    if ((threadIdx.x & 31) == 0) { s1[w] = s; s2[w] = ss; }
    __syncthreads();
    if (threadIdx.x == 0) {
        float S = 0.f, SS = 0.f;
        #pragma unroll
        for (int k = 0; k < 8; k++) { S += s1[k]; SS += s2[k]; }
        float mu = S / Hh;
        float var = SS / Hh - mu * mu;
        g_mu[row] = mu;
        g_rs[row] = rsqrtf(var + 1e-5f);
    }
}

// ---------------- LN1 apply + mask + transpose -> fp16 [B,H,L] ----------------
__global__ void ln1t_kernel(const float* __restrict__ x,
                            const float* __restrict__ w,
                            const float* __restrict__ bsh,
                            const int* __restrict__ mask) {
    __shared__ float tile[32][33];
    int b  = blockIdx.z;
    int l0 = blockIdx.x * 32, h0 = blockIdx.y * 32;
    int tx = threadIdx.x, ty = threadIdx.y;
    float wv = w[h0 + tx], bv = bsh[h0 + tx];
    #pragma unroll
    for (int k = 0; k < 4; k++) {
        int l   = l0 + ty + k * 8;
        int row = b * Ll + l;
        float v  = x[(size_t)row * Hh + h0 + tx];
        float mf = (float)mask[row];
        tile[ty + k * 8][tx] = ((v - g_mu[row]) * g_rs[row] * wv + bv) * mf;
    }
    __syncthreads();
    #pragma unroll
    for (int k = 0; k < 4; k++) {
        int h = h0 + ty + k * 8;
        g_uh[((size_t)b * Hh + h) * Ll + l0 + tx] = __float2half_rn(tile[tx][ty + k * 8]);
    }
}

// ---------------- S4D kernel K[2,H,L] precompute ----------------
__global__ void __launch_bounds__(64) kcomp_kernel(int layer,
                             const float* __restrict__ log_dt,
                             const float* __restrict__ A_re,
                             const float* __restrict__ A_im,
                             const float* __restrict__ C_re,
                             const float* __restrict__ C_im) {
    int h = blockIdx.x;
    __shared__ float s_ar[Nn], s_ai[Nn];
    __shared__ float s_sr[Nn], s_si[Nn];
    __shared__ float s_c0r[Nn], s_c0i[Nn], s_c1r[Nn], s_c1i[Nn];
    int t = threadIdx.x;
    {
        float dt = expf(log_dt[layer * Hh + h]);
        float Ar = -expf(A_re[((size_t)layer * Hh + h) * Nn + t]);
        float Ai = A_im[((size_t)layer * Hh + h) * Nn + t];
        float ar = dt * Ar, ai = dt * Ai;
        float er = expf(ar), sn, cs;
        sincosf(ai, &sn, &cs);
        float zr = er * cs - 1.0f, zi = er * sn;
        float den = Ar * Ar + Ai * Ai;
        float wr = (zr * Ar + zi * Ai) / den;
        float wi = (zi * Ar - zr * Ai) / den;
        size_t c0 = ((size_t)(layer * 2 + 0) * Hh + h) * Nn + t;
        size_t c1 = ((size_t)(layer * 2 + 1) * Hh + h) * Nn + t;
        float cr0 = C_re[c0], ci0 = C_im[c0];
        float cr1 = C_re[c1], ci1 = C_im[c1];
        s_ar[t] = ar; s_ai[t] = ai;
        s_sr[t] = er * cs; s_si[t] = er * sn;
        s_c0r[t] = cr0 * wr - ci0 * wi;  s_c0i[t] = cr0 * wi + ci0 * wr;
        s_c1r[t] = cr1 * wr - ci1 * wi;  s_c1i[t] = cr1 * wi + ci1 * wr;
    }
    __syncthreads();

    int l0 = t * 8;
    float fl0 = (float)l0;
    float k0a[8], k1a[8];
    #pragma unroll
    for (int j = 0; j < 8; j++) { k0a[j] = 0.f; k1a[j] = 0.f; }

    for (int n = 0; n < Nn; n++) {
        float ar = s_ar[n], ai = s_ai[n];
        float e0 = expf(ar * fl0);
        float sn, cs;
        sincosf(ai * fl0, &sn, &cs);
        float vr = e0 * cs, vi = e0 * sn;
        float sr = s_sr[n], si = s_si[n];
        float c0r = s_c0r[n], c0i = s_c0i[n];
        float c1r = s_c1r[n], c1i = s_c1i[n];
        #pragma unroll
        for (int j = 0; j < 8; j++) {
            k0a[j] += c0r * vr - c0i * vi;
            k1a[j] += c1r * vr - c1i * vi;
            float nvr = vr * sr - vi * si;
            float nvi = vr * si + vi * sr;
            vr = nvr; vi = nvi;
        }
    }
    #pragma unroll
    for (int j = 0; j < 8; j++) {
        g_K[(size_t)h * Ll + l0 + j]        = 2.0f * k0a[j];
        g_K[((size_t)Hh + h) * Ll + l0 + j] = 2.0f * k1a[j];
    }
}

// ---------------- conv via block-Toeplitz mma.sync fp16, fused D*u+GELU epilogue ----------------
#define USTRIDE 520          // halfs per us row (512 + 8 pad)
#define MSTRIDE 72           // halfs per M row
#define OFF_US 0             // 16 * 520 * 2  = 16640
#define OFF_CS 16640         // 1152 * 4      = 4608
#define OFF_M  21248         // 2 * 64*72*2   = 18432 -> 39680
#define CONV_SMEM 39936      // epilogue staging overlays [16640, 33280)

__device__ __forceinline__ void build_M(half* Mdst, const float* cs, int d, int t) {
    int p = t & 63, q0 = (t >> 6) * 16;
    int base = 576 + 64 * (d - 8) + q0 - p;
    half2 tmp[8];
    #pragma unroll
    for (int j = 0; j < 8; j++)
        tmp[j] = __floats2half2_rn(cs[base + 2 * j], cs[base + 2 * j + 1]);
    half2* dst = (half2*)(Mdst + p * MSTRIDE + q0);
    #pragma unroll
    for (int j = 0; j < 8; j++) dst[j] = tmp[j];
}

__global__ void __launch_bounds__(256) conv_tc_kernel(const float* __restrict__ Dvec) {
    extern __shared__ __align__(16) char sm[];
    half*  us = (half*)(sm + OFF_US);
    float* cs = (float*)(sm + OFF_CS);
    half*  M0 = (half*)(sm + OFF_M);
    half*  Ysh = (half*)(sm + OFF_CS);   // epilogue staging, overlays cs/M0
    uint32_t us_a = smem_u32(us);
    uint32_t m_a  = smem_u32(M0);

    int t = threadIdx.x, lane = t & 31, wid = t >> 5;
    int h = blockIdx.x >> 1, bh = (blockIdx.x & 1) * 16;

    // load u (16 batch rows) fp16, straight copy
    {
        int row = t >> 4, c0 = (t & 15) * 32;
        const uint4* src = (const uint4*)(g_uh + ((size_t)(bh + row) * Hh + h) * Ll + c0);
        uint4* dst = (uint4*)(us + row * USTRIDE + c0);
        #pragma unroll
        for (int j = 0; j < 4; j++) dst[j] = src[j];
    }
    // build c array: cs[576+dd]
    {
        const float* k0r = g_K + (size_t)h * Ll;
        const float* k1r = g_K + ((size_t)Hh + h) * Ll;
        float2 a = ((const float2*)k0r)[t];
        float2 b = ((const float2*)k1r)[t];
        cs[576 - 2 * t] = a.x;  cs[575 - 2 * t] = a.y;
        cs[577 + 2 * t] = b.x;  cs[578 + 2 * t] = b.y;
    }
    __syncthreads();

    float acc[4][2][4];
    #pragma unroll
    for (int i = 0; i < 4; i++)
        #pragma unroll
        for (int j = 0; j < 2; j++)
            #pragma unroll
            for (int q = 0; q < 4; q++) acc[i][j][q] = 0.f;

    build_M((half*)(sm + OFF_M + 9216), cs, 1, t);   // buf1 holds d=1
    __syncthreads();

    for (int d = 1; d <= 15; d++) {
        if (d < 15) build_M((half*)(sm + OFF_M + ((d & 1) ? 0 : 9216)), cs, d + 1, t);
        int jb = wid + d - 8;
        if (jb >= 0 && jb < 8) {
            uint32_t ma = m_a + ((d & 1) ? 9216u : 0u);
            #pragma unroll
            for (int ks = 0; ks < 4; ks++) {
                uint32_t ar[4][4];
                uint32_t abase = ma + (uint32_t)((lane & 15) * 144 + ks * 32 + (lane >> 4) * 16);
                #pragma unroll
                for (int mf = 0; mf < 4; mf++)
                    ldmx4(ar[mf], abase + (uint32_t)(mf * 16 * 144));
                int nrow = (lane & 7) + ((lane >> 4) & 1) * 8;
                uint32_t bd = us_a + (uint32_t)(nrow * 1040 + jb * 128 + ks * 32 + ((lane >> 3) & 1) * 16);
                uint32_t br[4];
                ldmx4(br, bd);
                #pragma unroll
                for (int mf = 0; mf < 4; mf++) {
                    mma_f16(acc[mf][0], ar[mf], br[0], br[1]);
                    mma_f16(acc[mf][1], ar[mf], br[2], br[3]);
                }
            }
        }
        __syncthreads();
    }

    // fused epilogue: y = gelu(conv + D*u), stage fp16 [b][l] (stride 520)
    float dv = Dvec[h];
    #pragma unroll
    for (int mf = 0; mf < 4; mf++) {
        int l = wid * 64 + mf * 16 + (lane >> 2);
        #pragma unroll
        for (int nf = 0; nf < 2; nf++) {
            int b = nf * 8 + (lane & 3) * 2;
            float u00 = __half2float(us[b * USTRIDE + l]);
            float u01 = __half2float(us[(b + 1) * USTRIDE + l]);
            float u10 = __half2float(us[b * USTRIDE + l + 8]);
            float u11 = __half2float(us[(b + 1) * USTRIDE + l + 8]);
            Ysh[b * 520 + l]           = __float2half_rn(gelu_tanh(acc[mf][nf][0] + dv * u00));
            Ysh[(b + 1) * 520 + l]     = __float2half_rn(gelu_tanh(acc[mf][nf][1] + dv * u01));
            Ysh[b * 520 + l + 8]       = __float2half_rn(gelu_tanh(acc[mf][nf][2] + dv * u10));
            Ysh[(b + 1) * 520 + l + 8] = __float2half_rn(gelu_tanh(acc[mf][nf][3] + dv * u11));
        }
    }
    __syncthreads();

    // coalesced in-place write back to g_uh [B,H,L]
    {
        int b = t >> 4, c = t & 15;
        half* orow = g_uh + ((size_t)(bh + b) * Hh + h) * Ll;
        #pragma unroll
        for (int p = 0; p < 4; p++) {
            int lo_ = c * 8 + p * 128;
            *(uint4*)&orow[lo_] = *(const uint4*)&Ysh[b * 520 + lo_];
        }
    }
}

// ---------------- Wout fp32 -> fp16 (all layers once) ----------------
__global__ void cvtw_kernel(const float* __restrict__ Wout) {
    int i = blockIdx.x * 256 + threadIdx.x;
    g_wh[i] = __float2half_rn(Wout[i]);
}

// ---------------- mma.sync fp16 GEMM: z[m,o] = sum_h y[m,h]*W[o,h] + bout[o] ----------------
// A read transposed from g_uh [B,H,L]: smem A tile = [32 k][128 m] (ldmatrix.trans).
#define AST 272                 // bytes per A k-row (256 data + 16 pad)
#define A_BYTES (32 * 272)      // 8704
#define B_BYTES (128 * 80)      // 10240
#define GST3 (A_BYTES + B_BYTES)

__device__ __forceinline__ void gemm_issue3(uint32_t sbase, const half* ybase, int o0, int k0,
                                            const half* wl, int tid) {
    // A: 32 rows (k) x 256B
    {
        int row = tid >> 4, c = tid & 15;
        #pragma unroll
        for (int p = 0; p < 4; p++) {
            int r = row + p * 8;
            cp16(sbase + (uint32_t)(r * AST + c * 16),
                 ybase + (size_t)(k0 + r) * Ll + c * 8);
        }
    }
    // B: 128 rows (o) x 64B
    {
        int r = tid >> 2, c4 = tid & 3;
        #pragma unroll
        for (int p = 0; p < 4; p++) {
            int row = r + p * 32;
            cp16(sbase + A_BYTES + (uint32_t)(row * 80 + c4 * 16),
                 wl + (size_t)(o0 + row) * Hh + k0 + c4 * 8);
        }
    }
}

__global__ void __launch_bounds__(128) gemm_mma_kernel(const half* __restrict__ wl,
                                                       const float* __restrict__ bout) {
    extern __shared__ __align__(16) char sm[];
    uint32_t s0 = smem_u32(sm);
    int tid = threadIdx.x, lane = tid & 31, wid = tid >> 5;
    int wm = wid & 1, wn = wid >> 1;
    int m0 = blockIdx.y * 128, o0 = blockIdx.x * 128;
    int b  = m0 >> 9, l0 = m0 & 511;
    const half* ybase = g_uh + (size_t)b * Hh * Ll + l0;

    float acc[4][8][4];
    #pragma unroll
    for (int i = 0; i < 4; i++)
        #pragma unroll
        for (int j = 0; j < 8; j++)
            #pragma unroll
            for (int q = 0; q < 4; q++) acc[i][j][q] = 0.f;

    gemm_issue3(s0, ybase, o0, 0, wl, tid);
    cp_commit();

    const int NCH = Hh / 32;   // 24
    for (int c = 0; c < NCH; c++) {
        int st = c & 1;
        if (c + 1 < NCH) {
            gemm_issue3(s0 + (st ^ 1) * GST3, ybase, o0, (c + 1) * 32, wl, tid);
            cp_commit();
            cp_wait1();
        } else {
            cp_wait0();
        }
        __syncthreads();

        uint32_t sA = s0 + st * GST3;
        uint32_t sB = sA + A_BYTES;
        int g2 = (lane >> 4);           // k +8 select
        int g1 = (lane >> 3) & 1;       // m +8 select
        int ki = lane & 7;
        #pragma unroll
        for (int ks = 0; ks < 2; ks++) {
            uint32_t a[4][4];
            #pragma unroll
            for (int mf = 0; mf < 4; mf++) {
                uint32_t aaddr = sA
                    + (uint32_t)((ks * 16 + g2 * 8 + ki) * AST
                                 + (wm * 64 + mf * 16 + g1 * 8) * 2);
                ldmx4t(a[mf], aaddr);
            }
            #pragma unroll
            for (int ng = 0; ng < 4; ng++) {
                int nrow = wn * 64 + ng * 16 + (lane & 7) + ((lane >> 4) & 1) * 8;
                uint32_t bd = sB + (uint32_t)(nrow * 80 + ks * 32 + ((lane >> 3) & 1) * 16);
                uint32_t bh[4];
                ldmx4(bh, bd);
                #pragma unroll
                for (int mf = 0; mf < 4; mf++) {
                    mma_f16(acc[mf][ng * 2],     a[mf], bh[0], bh[1]);
                    mma_f16(acc[mf][ng * 2 + 1], a[mf], bh[2], bh[3]);
                }
            }
        }
        __syncthreads();
    }

    #pragma unroll
    for (int mf = 0; mf < 4; mf++) {
        int mrow = m0 + wm * 64 + mf * 16 + (lane >> 2);
        #pragma unroll
        for (int nf = 0; nf < 8; nf++) {
            int ncol = o0 + wn * 64 + nf * 8 + (lane & 3) * 2;
            float b0 = bout[ncol], b1 = bout[ncol + 1];
            float* z0 = g_z + (size_t)mrow * Hh + ncol;
            float* z1 = g_z + (size_t)(mrow + 8) * Hh + ncol;
            *(float2*)z0 = make_float2(acc[mf][nf][0] + b0, acc[mf][nf][1] + b1);
            *(float2*)z1 = make_float2(acc[mf][nf][2] + b0, acc[mf][nf][3] + b1);
        }
    }
}

// ---------------- LN2 + residual + next-layer row stats ----------------
__global__ void ln2res_kernel(const float* __restrict__ w,
                              const float* __restrict__ bsh,
                              float* __restrict__ x) {
    int row = blockIdx.x;
    const float* zr = g_z + (size_t)row * Hh;
    float v[3];
    float s = 0.f, ss = 0.f;
    #pragma unroll
    for (int q = 0; q < 3; q++) {
        v[q] = zr[threadIdx.x + q * 256];
        s += v[q]; ss += v[q] * v[q];
    }
    for (int o = 16; o; o >>= 1) {
        s  += __shfl_down_sync(0xffffffffu, s, o);
        ss += __shfl_down_sync(0xffffffffu, ss, o);
    }
    __shared__ float s1[8], s2[8];
    __shared__ float smu, srs;
    int wi = threadIdx.x >> 5;
    if ((threadIdx.x & 31) == 0) { s1[wi] = s; s2[wi] = ss; }
    __syncthreads();
    if (threadIdx.x == 0) {
        float S = 0.f, SS = 0.f;
        #pragma unroll
        for (int k = 0; k < 8; k++) { S += s1[k]; SS += s2[k]; }
        float mu = S / Hh;
        float var = SS / Hh - mu * mu;
        smu = mu;
        srs = rsqrtf(var + 1e-5f);
    }
    __syncthreads();
    float mu = smu, rs = srs;
    float xn[3];
    float s2n = 0.f, ss2n = 0.f;
    #pragma unroll
    for (int q = 0; q < 3; q++) {
        int j = threadIdx.x + q * 256;
        size_t idx = (size_t)row * Hh + j;
        xn[q] = x[idx] + ((v[q] - mu) * rs * w[j] + bsh[j]);
        x[idx] = xn[q];
        s2n += xn[q]; ss2n += xn[q] * xn[q];
    }
    for (int o = 16; o; o >>= 1) {
        s2n  += __shfl_down_sync(0xffffffffu, s2n, o);
        ss2n += __shfl_down_sync(0xffffffffu, ss2n, o);
    }
    __syncthreads();
    if ((threadIdx.x & 31) == 0) { s1[wi] = s2n; s2[wi] = ss2n; }
    __syncthreads();
    if (threadIdx.x == 0) {
        float S = 0.f, SS = 0.f;
        #pragma unroll
        for (int k = 0; k < 8; k++) { S += s1[k]; SS += s2[k]; }
        float mun = S / Hh;
        float varn = SS / Hh - mun * mun;
        g_mu[row] = mun;
        g_rs[row] = rsqrtf(varn + 1e-5f);
    }
}

// ---------------- launch ----------------
extern "C" void kernel_launch(void* const* d_in, const int* in_sizes, int n_in,
                              void* d_out, int out_size) {
    const float* x_in   = (const float*)d_in[0];
    const int*   mask   = (const int*)  d_in[1];
    const float* ln1_w  = (const float*)d_in[2];
    const float* ln1_b  = (const float*)d_in[3];
    const float* log_dt = (const float*)d_in[4];
    const float* A_re   = (const float*)d_in[5];
    const float* A_im   = (const float*)d_in[6];
    const float* C_re   = (const float*)d_in[7];
    const float* C_im   = (const float*)d_in[8];
    const float* Dv     = (const float*)d_in[9];
    const float* Wout   = (const float*)d_in[10];
    const float* bout   = (const float*)d_in[11];
    const float* ln2_w  = (const float*)d_in[12];
    const float* ln2_b  = (const float*)d_in[13];
    float* x = (float*)d_out;

    cudaMemcpyAsync(x, x_in, sizeof(float) * (size_t)Bb * Ll * Hh,
                    cudaMemcpyDeviceToDevice, 0);
    cvtw_kernel<<<NLl * Hh * Hh / 256, 256>>>(Wout);
    rowstats_kernel<<<Bb * Ll, 256>>>(x);

    half* wh_base;
    cudaGetSymbolAddress((void**)&wh_base, g_wh);

    for (int i = 0; i < NLl; i++) {
        kcomp_kernel<<<Hh, 64>>>(i, log_dt, A_re, A_im, C_re, C_im);
        ln1t_kernel<<<dim3(Ll / 32, Hh / 32, Bb), dim3(32, 8)>>>(
            x, ln1_w + i * Hh, ln1_b + i * Hh, mask);
        conv_tc_kernel<<<Hh * 2, 256, CONV_SMEM>>>(Dv + i * Hh);
        gemm_mma_kernel<<<dim3(Hh / 128, Bb * Ll / 128), 128, 2 * GST3>>>(
            wh_base + (size_t)i * Hh * Hh, bout + i * Hh);
        ln2res_kernel<<<Bb * Ll, 256>>>(ln2_w + i * Hh, ln2_b + i * Hh, x);
    }
}